// round 3
// baseline (speedup 1.0000x reference)
#include <cuda_runtime.h>
#include <math.h>

// ---------------------------------------------------------------------------
// Problem constants
// ---------------------------------------------------------------------------
constexpr int Bb   = 8;
constexpr int Cc   = 128;
constexpr int N0   = 4096;       // H*W tokens
constexpr int MSGN = 4;
constexpr int NTOT = N0 + MSGN;  // 4100
constexpr int Wimg = 64;
constexpr int MTOT = Bb * NTOT;  // 32800
constexpr size_t OUT2_OFS = (size_t)Bb * N0 * Cc;  // start of msg-token output part

template <int BR> struct BrCfg;
template <> struct BrCfg<0> {
    static constexpr int S = 4, WR = 16, L = 256, LM = 260, K = 2048, NSPLIT = 8, M = Bb * 260;
};
template <> struct BrCfg<1> {
    static constexpr int S = 2, WR = 32, L = 1024, LM = 1028, K = 512, NSPLIT = 2, M = Bb * 1028;
};

// ---------------------------------------------------------------------------
// Scratch (device globals — no allocation allowed)
// ---------------------------------------------------------------------------
__device__ float g_q  [MTOT * Cc];
__device__ float g_cat[MTOT * Cc];
__device__ float g_w1r[128 * 2048];
__device__ float g_w2r[128 * 512];
__device__ float g_p1 [8 * 2080 * 128];
__device__ float g_p2 [2 * 8224 * 128];
__device__ float g_xk1[2080 * 128];
__device__ float g_xk2[8224 * 128];
__device__ float g_k1 [2080 * 64];
__device__ float g_vt1[2080 * 64];
__device__ float g_v1 [2080 * 64];
__device__ float g_k2 [8224 * 64];
__device__ float g_vt2[8224 * 64];
__device__ float g_v2 [8224 * 64];

// ---------------------------------------------------------------------------
// Weight repack: sr_w[o][c][p]  ->  wr[o][p*128 + c]   (p = i*S + j)
// Makes A-tile loads of the SR GEMM contiguous in c.
// ---------------------------------------------------------------------------
template <int BR>
__global__ void repack_k(const float* __restrict__ src) {
    constexpr int P = BrCfg<BR>::K / 128;
    int idx = blockIdx.x * 256 + threadIdx.x;
    if (idx >= 128 * P * 128) return;
    int o = idx / (P * 128);
    int rem = idx % (P * 128);
    int p = rem / 128;
    int c = rem % 128;
    float* dst = BR ? g_w2r : g_w1r;
    dst[idx] = src[(o * 128 + c) * P + p];
}

// ---------------------------------------------------------------------------
// Generic tiled GEMM: C[M,128] = A[M,K] @ W[128,K]^T  (+epilogue per MODE)
//  MODE 0: Q projection    A = concat(x, msg) rows        -> g_q (+bias)
//  MODE 1: SR conv (split-K partials, A gathered patches) -> g_p{1,2}
//  MODE 2: KV projection   A = g_xk                       -> g_k / g_vt (+bias)
//  MODE 3: out projection  A = g_cat                      -> d_out (+bias+residual, split)
// Tile: BM=128, BN=128, BK=32; 256 threads, 8x8 micro-tile, float4 smem reads.
// ---------------------------------------------------------------------------
template <int MODE, int BR>
__global__ void __launch_bounds__(256) gemm_k(
    const float* __restrict__ x, const float* __restrict__ msg,
    const float* __restrict__ Wext, const float* __restrict__ bias,
    float* __restrict__ outext, int M, int Ktot, int Ks)
{
    constexpr int AST = 132;
    __shared__ __align__(16) float sA[32 * AST];
    __shared__ __align__(16) float sW[32 * AST];

    const int tid   = threadIdx.x;
    const int tileM = blockIdx.x * 128;
    const int kb    = blockIdx.y * Ks;

    const float* Wp = (MODE == 1) ? (BR ? g_w2r : g_w1r) : Wext;

    const int lane = tid & 7;    // 8 lanes * float4 = 32 K-values
    const int rq   = tid >> 3;   // 0..31 row quad

    const float* abase[4];
    bool avalid[4], aspat[4];
#pragma unroll
    for (int ps = 0; ps < 4; ++ps) {
        int grow = tileM + ps * 32 + rq;
        bool val = grow < M;
        avalid[ps] = val;
        aspat[ps]  = true;
        int g2 = val ? grow : 0;
        if (MODE == 0) {
            int b = g2 / NTOT, n = g2 % NTOT;
            abase[ps] = (n < N0)
                ? x   + (size_t)(b * N0   + n)        * 128 + lane * 4
                : msg + (size_t)(b * MSGN + (n - N0)) * 128 + lane * 4;
        } else if (MODE == 2) {
            const float* A = BR ? g_xk2 : g_xk1;
            abase[ps] = A + (size_t)g2 * 128 + lane * 4;
        } else if (MODE == 3) {
            abase[ps] = g_cat + (size_t)g2 * 128 + lane * 4;
        } else {  // MODE 1: SR patch gather
            constexpr int LMc = BrCfg<BR>::LM, Lc = BrCfg<BR>::L;
            constexpr int WRc = BrCfg<BR>::WR, Sc = BrCfg<BR>::S;
            int b = g2 / LMc, l = g2 % LMc;
            if (l < Lc) {
                int hr = l / WRc, wr = l % WRc;
                abase[ps] = x + (size_t)(b * N0 + (hr * Sc) * Wimg + wr * Sc) * 128 + lane * 4;
            } else {
                abase[ps] = msg + (size_t)(b * MSGN + (l - Lc)) * 128 + lane * 4;
                aspat[ps] = false;  // msg row: same data for every patch position p
            }
        }
    }

    const int tx = tid & 15;   // 16 -> cols tx*8..tx*8+7
    const int ty = tid >> 4;   // 16 -> rows ty*8..ty*8+7
    float acc[8][8];
#pragma unroll
    for (int i = 0; i < 8; ++i)
#pragma unroll
        for (int j = 0; j < 8; ++j) acc[i][j] = 0.f;

    for (int k0 = kb; k0 < kb + Ks; k0 += 32) {
        // --- load W tile (transposed into sW[k][n]) ---
#pragma unroll
        for (int ps = 0; ps < 4; ++ps) {
            int n = ps * 32 + rq;
            float4 w = *(const float4*)(Wp + (size_t)n * Ktot + k0 + lane * 4);
            sW[(lane * 4 + 0) * AST + n] = w.x;
            sW[(lane * 4 + 1) * AST + n] = w.y;
            sW[(lane * 4 + 2) * AST + n] = w.z;
            sW[(lane * 4 + 3) * AST + n] = w.w;
        }
        // --- load A tile (transposed into sA[k][m]) ---
        int aofs_s = k0, aofs_m = k0;
        if (MODE == 1) {
            constexpr int Sc = BrCfg<BR>::S;
            int p = k0 >> 7, c0 = k0 & 127;
            aofs_s = ((p / Sc) * Wimg + (p % Sc)) * 128 + c0;
            aofs_m = c0;
        }
#pragma unroll
        for (int ps = 0; ps < 4; ++ps) {
            int row = ps * 32 + rq;
            float4 a = make_float4(0.f, 0.f, 0.f, 0.f);
            if (avalid[ps])
                a = *(const float4*)(abase[ps] + (aspat[ps] ? aofs_s : aofs_m));
            sA[(lane * 4 + 0) * AST + row] = a.x;
            sA[(lane * 4 + 1) * AST + row] = a.y;
            sA[(lane * 4 + 2) * AST + row] = a.z;
            sA[(lane * 4 + 3) * AST + row] = a.w;
        }
        __syncthreads();
#pragma unroll 4
        for (int kk = 0; kk < 32; ++kk) {
            const float4* a4 = (const float4*)(sA + kk * AST);
            const float4* w4 = (const float4*)(sW + kk * AST);
            float4 A0 = a4[2 * ty], A1 = a4[2 * ty + 1];
            float4 W0 = w4[2 * tx], W1 = w4[2 * tx + 1];
            float av[8] = {A0.x, A0.y, A0.z, A0.w, A1.x, A1.y, A1.z, A1.w};
            float wv[8] = {W0.x, W0.y, W0.z, W0.w, W1.x, W1.y, W1.z, W1.w};
#pragma unroll
            for (int ii = 0; ii < 8; ++ii)
#pragma unroll
                for (int jj = 0; jj < 8; ++jj)
                    acc[ii][jj] = fmaf(av[ii], wv[jj], acc[ii][jj]);
        }
        __syncthreads();
    }

    // --- epilogue ---
    const int colb = tx * 8;
    float bsv[8];
    if (MODE != 1) {
#pragma unroll
        for (int jj = 0; jj < 8; ++jj) bsv[jj] = bias[colb + jj];
    }
#pragma unroll
    for (int ii = 0; ii < 8; ++ii) {
        int r = tileM + ty * 8 + ii;
        if (r >= M) continue;
        if (MODE == 0) {
            float* o = g_q + (size_t)r * 128 + colb;
#pragma unroll
            for (int jj = 0; jj < 8; ++jj) o[jj] = acc[ii][jj] + bsv[jj];
        } else if (MODE == 1) {
            float* o = (BR ? g_p2 : g_p1) + ((size_t)blockIdx.y * M + r) * 128 + colb;
#pragma unroll
            for (int jj = 0; jj < 8; ++jj) o[jj] = acc[ii][jj];
        } else if (MODE == 2) {
            float* o = (colb < 64)
                ? (BR ? g_k2  : g_k1 ) + (size_t)r * 64 + colb
                : (BR ? g_vt2 : g_vt1) + (size_t)r * 64 + (colb - 64);
#pragma unroll
            for (int jj = 0; jj < 8; ++jj) o[jj] = acc[ii][jj] + bsv[jj];
        } else {  // MODE 3: bias + residual + split store
            int b = r / NTOT, n = r % NTOT;
            const float* res;
            float* o;
            if (n < N0) {
                res = x      + (size_t)(b * N0 + n) * 128 + colb;
                o   = outext + (size_t)(b * N0 + n) * 128 + colb;
            } else {
                res = msg    + (size_t)(b * MSGN + (n - N0)) * 128 + colb;
                o   = outext + OUT2_OFS + (size_t)(b * MSGN + (n - N0)) * 128 + colb;
            }
#pragma unroll
            for (int jj = 0; jj < 8; ++jj) o[jj] = acc[ii][jj] + bsv[jj] + res[jj];
        }
    }
}

// ---------------------------------------------------------------------------
// Split-K reduce + bias + LayerNorm + exact GELU  ->  g_xk
// 1 warp per row (128 cols, 4 per lane).
// ---------------------------------------------------------------------------
template <int BR>
__global__ void sr_finish(const float* __restrict__ bias, const float* __restrict__ lng,
                          const float* __restrict__ lnb)
{
    constexpr int M  = BrCfg<BR>::M;
    constexpr int NS = BrCfg<BR>::NSPLIT;
    const float* part = BR ? g_p2 : g_p1;
    float* out        = BR ? g_xk2 : g_xk1;

    int warp  = threadIdx.x >> 5;
    int lanei = threadIdx.x & 31;
    int r = blockIdx.x * 8 + warp;
    if (r >= M) return;

    float v[4];
    {
        float4 a = *(const float4*)(part + (size_t)r * 128 + lanei * 4);
        v[0] = a.x; v[1] = a.y; v[2] = a.z; v[3] = a.w;
    }
#pragma unroll
    for (int s = 1; s < NS; ++s) {
        float4 a = *(const float4*)(part + ((size_t)s * M + r) * 128 + lanei * 4);
        v[0] += a.x; v[1] += a.y; v[2] += a.z; v[3] += a.w;
    }
    {
        float4 bv = *(const float4*)(bias + lanei * 4);
        v[0] += bv.x; v[1] += bv.y; v[2] += bv.z; v[3] += bv.w;
    }
    float sum = v[0] + v[1] + v[2] + v[3];
    float sq  = v[0]*v[0] + v[1]*v[1] + v[2]*v[2] + v[3]*v[3];
#pragma unroll
    for (int ofs = 16; ofs >= 1; ofs >>= 1) {
        sum += __shfl_xor_sync(0xffffffffu, sum, ofs);
        sq  += __shfl_xor_sync(0xffffffffu, sq,  ofs);
    }
    float mean = sum * (1.f / 128.f);
    float var  = sq  * (1.f / 128.f) - mean * mean;
    float rstd = rsqrtf(var + 1e-5f);

    float4 gg = *(const float4*)(lng + lanei * 4);
    float4 bb = *(const float4*)(lnb + lanei * 4);
    float gv[4] = {gg.x, gg.y, gg.z, gg.w};
    float bv2[4] = {bb.x, bb.y, bb.z, bb.w};
    float ov[4];
#pragma unroll
    for (int q2 = 0; q2 < 4; ++q2) {
        float t = (v[q2] - mean) * rstd * gv[q2] + bv2[q2];
        ov[q2] = 0.5f * t * (1.f + erff(t * 0.70710678118654752f));
    }
    *(float4*)(out + (size_t)r * 128 + lanei * 4) = make_float4(ov[0], ov[1], ov[2], ov[3]);
}

// ---------------------------------------------------------------------------
// V fix-up: spatial rows -> v + dwconv3x3(v) + lc_b ; msg rows -> 2*v
// ---------------------------------------------------------------------------
template <int BR>
__global__ void lc_k(const float* __restrict__ lw, const float* __restrict__ lb)
{
    constexpr int LM = BrCfg<BR>::LM, L = BrCfg<BR>::L, WR = BrCfg<BR>::WR;
    const float* vt = BR ? g_vt2 : g_vt1;
    float* vo       = BR ? g_v2  : g_v1;
    int idx = blockIdx.x * 256 + threadIdx.x;
    if (idx >= Bb * LM * 64) return;
    int ch   = idx & 63;
    int rest = idx >> 6;
    int l = rest % LM, b = rest / LM;
    float c = vt[idx];
    if (l >= L) { vo[idx] = 2.f * c; return; }
    int hr = l / WR, wr = l % WR;
    float a = lb[ch];
#pragma unroll
    for (int di = 0; di < 3; ++di)
#pragma unroll
        for (int dj = 0; dj < 3; ++dj) {
            int nh = hr + di - 1, nw = wr + dj - 1;
            if (nh >= 0 && nh < WR && nw >= 0 && nw < WR)
                a += vt[((size_t)(b * LM) + nh * WR + nw) * 64 + ch] * lw[ch * 9 + di * 3 + dj];
        }
    vo[idx] = c + a;
}

// ---------------------------------------------------------------------------
// Flash attention: 1 query/thread, 128 queries/block, K/V streamed in 32-row
// smem chunks with online softmax.  grid = (ceil(N/128), B*2 heads)
// ---------------------------------------------------------------------------
template <int BR>
__global__ void __launch_bounds__(128) attn_k()
{
    constexpr int LM   = BrCfg<BR>::LM;
    constexpr int QOFS = BR ? 64 : 0;
    constexpr float SCALE = 0.17677669529663687f;  // 32^-0.5
    const float* gk = BR ? g_k2 : g_k1;
    const float* gv = BR ? g_v2 : g_v1;

    const int b   = blockIdx.y >> 1;
    const int h   = blockIdx.y & 1;
    const int tid = threadIdx.x;
    const int qrow = blockIdx.x * 128 + tid;
    const bool qv  = qrow < NTOT;
    const int  qr  = qv ? qrow : NTOT - 1;

    float q[32];
    {
        const float4* qp = (const float4*)(g_q + (size_t)(b * NTOT + qr) * 128 + QOFS + h * 32);
#pragma unroll
        for (int i = 0; i < 8; ++i) {
            float4 t = qp[i];
            q[4*i] = t.x; q[4*i+1] = t.y; q[4*i+2] = t.z; q[4*i+3] = t.w;
        }
    }
    float o[32];
#pragma unroll
    for (int i = 0; i < 32; ++i) o[i] = 0.f;
    float mrun = -1e30f, lsum = 0.f;

    __shared__ __align__(16) float Ks[32 * 32];
    __shared__ __align__(16) float Vs[32 * 32];
    const int lane = tid & 7, r8 = tid >> 3;

    for (int c0 = 0; c0 < LM; c0 += 32) {
        __syncthreads();
#pragma unroll
        for (int ps = 0; ps < 2; ++ps) {
            int kr = ps * 16 + r8;
            int src = c0 + kr;
            float4 kk4 = make_float4(0.f, 0.f, 0.f, 0.f);
            float4 vv4 = make_float4(0.f, 0.f, 0.f, 0.f);
            if (src < LM) {
                size_t base = (size_t)(b * LM + src) * 64 + h * 32 + lane * 4;
                kk4 = *(const float4*)(gk + base);
                vv4 = *(const float4*)(gv + base);
            }
            *(float4*)(Ks + kr * 32 + lane * 4) = kk4;
            *(float4*)(Vs + kr * 32 + lane * 4) = vv4;
        }
        __syncthreads();

        const int lim = LM - c0;
        float s[32];
#pragma unroll 4
        for (int kk = 0; kk < 32; ++kk) {
            const float4* kp = (const float4*)(Ks + kk * 32);
            float d = 0.f;
#pragma unroll
            for (int i = 0; i < 8; ++i) {
                float4 t = kp[i];
                d = fmaf(q[4*i],   t.x, d);
                d = fmaf(q[4*i+1], t.y, d);
                d = fmaf(q[4*i+2], t.z, d);
                d = fmaf(q[4*i+3], t.w, d);
            }
            s[kk] = (kk < lim) ? d * SCALE : -1e30f;
        }
        float mloc = s[0];
#pragma unroll
        for (int kk = 1; kk < 32; ++kk) mloc = fmaxf(mloc, s[kk]);
        float mnew = fmaxf(mrun, mloc);
        float corr = __expf(mrun - mnew);
        lsum *= corr;
#pragma unroll
        for (int i = 0; i < 32; ++i) o[i] *= corr;
        float ls = 0.f;
#pragma unroll
        for (int kk = 0; kk < 32; ++kk) {
            float p = __expf(s[kk] - mnew);
            s[kk] = p;
            ls += p;
        }
        lsum += ls;
#pragma unroll 4
        for (int kk = 0; kk < 32; ++kk) {
            float p = s[kk];
            const float4* vp = (const float4*)(Vs + kk * 32);
#pragma unroll
            for (int i = 0; i < 8; ++i) {
                float4 t = vp[i];
                o[4*i]   = fmaf(p, t.x, o[4*i]);
                o[4*i+1] = fmaf(p, t.y, o[4*i+1]);
                o[4*i+2] = fmaf(p, t.z, o[4*i+2]);
                o[4*i+3] = fmaf(p, t.w, o[4*i+3]);
            }
        }
        mrun = mnew;
    }

    if (qv) {
        float inv = 1.f / lsum;
        float4* op = (float4*)(g_cat + (size_t)(b * NTOT + qrow) * 128 + QOFS + h * 32);
#pragma unroll
        for (int i = 0; i < 8; ++i)
            op[i] = make_float4(o[4*i] * inv, o[4*i+1] * inv, o[4*i+2] * inv, o[4*i+3] * inv);
    }
}

// ---------------------------------------------------------------------------
// Launch
// ---------------------------------------------------------------------------
extern "C" void kernel_launch(void* const* d_in, const int* in_sizes, int n_in,
                              void* d_out, int out_size)
{
    (void)in_sizes; (void)n_in; (void)out_size;
    const float* x     = (const float*)d_in[0];
    const float* msg   = (const float*)d_in[1];
    const float* Wq    = (const float*)d_in[2];
    const float* bq    = (const float*)d_in[3];
    const float* sr1w  = (const float*)d_in[4];
    const float* sr1b  = (const float*)d_in[5];
    const float* ln1g  = (const float*)d_in[6];
    const float* ln1b  = (const float*)d_in[7];
    const float* sr2w  = (const float*)d_in[8];
    const float* sr2b  = (const float*)d_in[9];
    const float* ln2g  = (const float*)d_in[10];
    const float* ln2b  = (const float*)d_in[11];
    const float* kv1w  = (const float*)d_in[12];
    const float* kv1b  = (const float*)d_in[13];
    const float* kv2w  = (const float*)d_in[14];
    const float* kv2b  = (const float*)d_in[15];
    const float* lc1w  = (const float*)d_in[16];
    const float* lc1b  = (const float*)d_in[17];
    const float* lc2w  = (const float*)d_in[18];
    const float* lc2b  = (const float*)d_in[19];
    const float* projw = (const float*)d_in[20];
    const float* projb = (const float*)d_in[21];
    float* out = (float*)d_out;

    // Weight repack for SR convs
    repack_k<0><<<(128 * 2048 + 255) / 256, 256>>>(sr1w);
    repack_k<1><<<(128 * 512  + 255) / 256, 256>>>(sr2w);

    // Q projection over concat(x, msg)
    gemm_k<0, 0><<<257, 256>>>(x, msg, Wq, bq, nullptr, MTOT, 128, 128);

    // SR convs as split-K GEMMs -> partials
    gemm_k<1, 0><<<dim3(17, 8), 256>>>(x, msg, nullptr, nullptr, nullptr, 2080, 2048, 256);
    gemm_k<1, 1><<<dim3(65, 2), 256>>>(x, msg, nullptr, nullptr, nullptr, 8224, 512, 256);

    // Reduce + bias + LN + GELU
    sr_finish<0><<<(2080 + 7) / 8, 256>>>(sr1b, ln1g, ln1b);
    sr_finish<1><<<(8224 + 7) / 8, 256>>>(sr2b, ln2g, ln2b);

    // KV projections (k -> g_k, v -> g_vt)
    gemm_k<2, 0><<<17, 256>>>(x, msg, kv1w, kv1b, nullptr, 2080, 128, 128);
    gemm_k<2, 1><<<65, 256>>>(x, msg, kv2w, kv2b, nullptr, 8224, 128, 128);

    // Depthwise 3x3 fix-up of V (msg rows doubled)
    lc_k<0><<<(2080 * 64 + 255) / 256, 256>>>(lc1w, lc1b);
    lc_k<1><<<(8224 * 64 + 255) / 256, 256>>>(lc2w, lc2b);

    // Flash attention, both branches -> g_cat
    attn_k<0><<<dim3(33, 16), 128>>>();
    attn_k<1><<<dim3(33, 16), 128>>>();

    // Output projection + residual + split store
    gemm_k<3, 0><<<257, 256>>>(x, msg, projw, projb, out, MTOT, 128, 128);
}

// round 5
// speedup vs baseline: 1.1651x; 1.1651x over previous
#include <cuda_runtime.h>
#include <math.h>

typedef unsigned long long ull;

// ---------------------------------------------------------------------------
// Packed f32x2 helpers (Blackwell FFMA2 path — ptxas never emits these itself)
// ---------------------------------------------------------------------------
__device__ __forceinline__ ull ffma2(ull a, ull b, ull c) {
    ull d;
    asm("fma.rn.f32x2 %0, %1, %2, %3;" : "=l"(d) : "l"(a), "l"(b), "l"(c));
    return d;
}
__device__ __forceinline__ ull fmul2(ull a, ull b) {
    ull d;
    asm("mul.rn.f32x2 %0, %1, %2;" : "=l"(d) : "l"(a), "l"(b));
    return d;
}
__device__ __forceinline__ ull pack2(float x) {
    ull r; unsigned u = __float_as_uint(x);
    asm("mov.b64 %0, {%1, %1};" : "=l"(r) : "r"(u));
    return r;
}
__device__ __forceinline__ float2 unpack2(ull v) {
    float2 r;
    asm("mov.b64 {%0, %1}, %2;" : "=f"(r.x), "=f"(r.y) : "l"(v));
    return r;
}

// ---------------------------------------------------------------------------
// Problem constants
// ---------------------------------------------------------------------------
constexpr int Bb   = 8;
constexpr int Cc   = 128;
constexpr int N0   = 4096;
constexpr int MSGN = 4;
constexpr int NTOT = N0 + MSGN;  // 4100
constexpr int Wimg = 64;
constexpr int MTOT = Bb * NTOT;  // 32800
constexpr size_t OUT2_OFS = (size_t)Bb * N0 * Cc;
constexpr int AST = 132;

template <int BR> struct BrCfg;
template <> struct BrCfg<0> {
    static constexpr int S = 4, WR = 16, L = 256, LM = 260, K = 2048, NSPLIT = 8, M = Bb * 260;
};
template <> struct BrCfg<1> {
    static constexpr int S = 2, WR = 32, L = 1024, LM = 1028, K = 512, NSPLIT = 2, M = Bb * 1028;
};

// ---------------------------------------------------------------------------
// Scratch (device globals — no allocation allowed)
// ---------------------------------------------------------------------------
__device__ float g_q  [MTOT * Cc];
__device__ float g_cat[MTOT * Cc];
__device__ float g_w1r[128 * 2048];
__device__ float g_w2r[128 * 512];
__device__ float g_p1 [8 * 2080 * 128];
__device__ float g_p2 [2 * 8224 * 128];
__device__ float g_xk1[2080 * 128];
__device__ float g_xk2[8224 * 128];
__device__ float g_k1 [2080 * 64];
__device__ float g_vt1[2080 * 64];
__device__ float g_v1 [2080 * 64];
__device__ float g_k2 [8224 * 64];
__device__ float g_vt2[8224 * 64];
__device__ float g_v2 [8224 * 64];

// ---------------------------------------------------------------------------
// Weight repack (both SR convs in one launch):
//   sr_w[o][c][p]  ->  wr[o][p*128 + c]
// ---------------------------------------------------------------------------
__global__ void repack_all(const float* __restrict__ s1, const float* __restrict__ s2) {
    int idx = blockIdx.x * 256 + threadIdx.x;
    constexpr int T1 = 128 * 16 * 128;  // 262144
    constexpr int T2 = 128 * 4  * 128;  // 65536
    if (idx < T1) {
        int o = idx / (16 * 128);
        int rem = idx % (16 * 128);
        int p = rem / 128, c = rem % 128;
        g_w1r[idx] = s1[(o * 128 + c) * 16 + p];
    } else if (idx < T1 + T2) {
        int j = idx - T1;
        int o = j / (4 * 128);
        int rem = j % (4 * 128);
        int p = rem / 128, c = rem % 128;
        g_w2r[j] = s2[(o * 128 + c) * 4 + p];
    }
}

// ---------------------------------------------------------------------------
// Generic tiled GEMM device function: C[M,128] = A[M,K] @ W[128,K]^T
//  MODE 0: Q proj  -> g_q (+bias)
//  MODE 1: SR conv split-K partials -> g_p{1,2}
//  MODE 2: KV proj -> g_k / g_vt (+bias)
//  MODE 3: out proj -> d_out (+bias + residual, split store)
// 128x128x32 tile, 256 thr, 8x8 micro-tile via FFMA2 (8x4 packed acc).
// ---------------------------------------------------------------------------
template <int MODE, int BR>
__device__ __forceinline__ void gemm_dev(
    float* sA, float* sW,
    const float* __restrict__ x, const float* __restrict__ msg,
    const float* __restrict__ Wext, const float* __restrict__ bias,
    float* __restrict__ outext,
    int M, int Ktot, int tileM, int kb, int Ks, int splitIdx)
{
    const int tid = threadIdx.x;
    const float* Wp = (MODE == 1) ? (BR ? g_w2r : g_w1r) : Wext;

    const int lane = tid & 7;   // 8 lanes * float4 = 32 K-values
    const int rq   = tid >> 3;  // 0..31

    const float* abase[4];
    bool avalid[4], aspat[4];
#pragma unroll
    for (int ps = 0; ps < 4; ++ps) {
        int grow = tileM + ps * 32 + rq;
        bool val = grow < M;
        avalid[ps] = val;
        aspat[ps]  = true;
        int g2 = val ? grow : 0;
        if (MODE == 0) {
            int b = g2 / NTOT, n = g2 % NTOT;
            abase[ps] = (n < N0)
                ? x   + (size_t)(b * N0   + n)        * 128 + lane * 4
                : msg + (size_t)(b * MSGN + (n - N0)) * 128 + lane * 4;
        } else if (MODE == 2) {
            const float* A = BR ? g_xk2 : g_xk1;
            abase[ps] = A + (size_t)g2 * 128 + lane * 4;
        } else if (MODE == 3) {
            abase[ps] = g_cat + (size_t)g2 * 128 + lane * 4;
        } else {  // MODE 1: SR patch gather
            constexpr int LMc = BrCfg<BR>::LM, Lc = BrCfg<BR>::L;
            constexpr int WRc = BrCfg<BR>::WR, Sc = BrCfg<BR>::S;
            int b = g2 / LMc, l = g2 % LMc;
            if (l < Lc) {
                int hr = l / WRc, wr = l % WRc;
                abase[ps] = x + (size_t)(b * N0 + (hr * Sc) * Wimg + wr * Sc) * 128 + lane * 4;
            } else {
                abase[ps] = msg + (size_t)(b * MSGN + (l - Lc)) * 128 + lane * 4;
                aspat[ps] = false;
            }
        }
    }

    const int tx = tid & 15;   // cols tx*8..tx*8+7
    const int ty = tid >> 4;   // rows ty*8..ty*8+7
    ull acc2[8][4];
#pragma unroll
    for (int i = 0; i < 8; ++i)
#pragma unroll
        for (int j = 0; j < 4; ++j) acc2[i][j] = 0ull;

    for (int k0 = kb; k0 < kb + Ks; k0 += 32) {
        // W tile -> sW[k][n]
#pragma unroll
        for (int ps = 0; ps < 4; ++ps) {
            int n = ps * 32 + rq;
            float4 w = *(const float4*)(Wp + (size_t)n * Ktot + k0 + lane * 4);
            sW[(lane * 4 + 0) * AST + n] = w.x;
            sW[(lane * 4 + 1) * AST + n] = w.y;
            sW[(lane * 4 + 2) * AST + n] = w.z;
            sW[(lane * 4 + 3) * AST + n] = w.w;
        }
        // A tile -> sA[k][m]
        int aofs_s = k0, aofs_m = k0;
        if (MODE == 1) {
            constexpr int Sc = BrCfg<BR>::S;
            int p = k0 >> 7, c0 = k0 & 127;
            aofs_s = ((p / Sc) * Wimg + (p % Sc)) * 128 + c0;
            aofs_m = c0;
        }
#pragma unroll
        for (int ps = 0; ps < 4; ++ps) {
            int row = ps * 32 + rq;
            float4 a = make_float4(0.f, 0.f, 0.f, 0.f);
            if (avalid[ps])
                a = *(const float4*)(abase[ps] + (aspat[ps] ? aofs_s : aofs_m));
            sA[(lane * 4 + 0) * AST + row] = a.x;
            sA[(lane * 4 + 1) * AST + row] = a.y;
            sA[(lane * 4 + 2) * AST + row] = a.z;
            sA[(lane * 4 + 3) * AST + row] = a.w;
        }
        __syncthreads();
#pragma unroll 4
        for (int kk = 0; kk < 32; ++kk) {
            const float4*     a4 = (const float4*)(sA + kk * AST);
            const ulonglong2* w8 = (const ulonglong2*)(sW + kk * AST);
            float4 A0 = a4[2 * ty], A1 = a4[2 * ty + 1];
            ulonglong2 Wa = w8[2 * tx], Wb = w8[2 * tx + 1];
            ull wv2[4] = {Wa.x, Wa.y, Wb.x, Wb.y};
            float av[8] = {A0.x, A0.y, A0.z, A0.w, A1.x, A1.y, A1.z, A1.w};
#pragma unroll
            for (int ii = 0; ii < 8; ++ii) {
                ull a2 = pack2(av[ii]);
#pragma unroll
                for (int j2 = 0; j2 < 4; ++j2)
                    acc2[ii][j2] = ffma2(a2, wv2[j2], acc2[ii][j2]);
            }
        }
        __syncthreads();
    }

    // unpack accumulator
    float acc[8][8];
#pragma unroll
    for (int ii = 0; ii < 8; ++ii)
#pragma unroll
        for (int j2 = 0; j2 < 4; ++j2) {
            float2 f = unpack2(acc2[ii][j2]);
            acc[ii][2 * j2]     = f.x;
            acc[ii][2 * j2 + 1] = f.y;
        }

    // epilogue
    const int colb = tx * 8;
    float bsv[8];
    if (MODE != 1) {
#pragma unroll
        for (int jj = 0; jj < 8; ++jj) bsv[jj] = bias[colb + jj];
    }
#pragma unroll
    for (int ii = 0; ii < 8; ++ii) {
        int r = tileM + ty * 8 + ii;
        if (r >= M) continue;
        if (MODE == 0) {
            float* o = g_q + (size_t)r * 128 + colb;
#pragma unroll
            for (int jj = 0; jj < 8; ++jj) o[jj] = acc[ii][jj] + bsv[jj];
        } else if (MODE == 1) {
            float* o = (BR ? g_p2 : g_p1) + ((size_t)splitIdx * M + r) * 128 + colb;
#pragma unroll
            for (int jj = 0; jj < 8; ++jj) o[jj] = acc[ii][jj];
        } else if (MODE == 2) {
            float* o = (colb < 64)
                ? (BR ? g_k2  : g_k1 ) + (size_t)r * 64 + colb
                : (BR ? g_vt2 : g_vt1) + (size_t)r * 64 + (colb - 64);
#pragma unroll
            for (int jj = 0; jj < 8; ++jj) o[jj] = acc[ii][jj] + bsv[jj];
        } else {
            int b = r / NTOT, n = r % NTOT;
            const float* res;
            float* o;
            if (n < N0) {
                res = x      + (size_t)(b * N0 + n) * 128 + colb;
                o   = outext + (size_t)(b * N0 + n) * 128 + colb;
            } else {
                res = msg    + (size_t)(b * MSGN + (n - N0)) * 128 + colb;
                o   = outext + OUT2_OFS + (size_t)(b * MSGN + (n - N0)) * 128 + colb;
            }
#pragma unroll
            for (int jj = 0; jj < 8; ++jj) o[jj] = acc[ii][jj] + bsv[jj] + res[jj];
        }
    }
}

// ---------------------------------------------------------------------------
// Phase-1 fused kernel: SR1 split-K (136 CTAs) + SR2 split-K (130) + Qproj (257)
// ---------------------------------------------------------------------------
__global__ void __launch_bounds__(256, 2) phase1_k(
    const float* __restrict__ x, const float* __restrict__ msg,
    const float* __restrict__ Wq, const float* __restrict__ bq)
{
    __shared__ __align__(16) float sA[32 * AST];
    __shared__ __align__(16) float sW[32 * AST];
    int bx = blockIdx.x;
    if (bx < 136) {
        gemm_dev<1, 0>(sA, sW, x, msg, nullptr, nullptr, nullptr,
                       2080, 2048, (bx % 17) * 128, (bx / 17) * 256, 256, bx / 17);
    } else if (bx < 266) {
        int t = bx - 136;
        gemm_dev<1, 1>(sA, sW, x, msg, nullptr, nullptr, nullptr,
                       8224, 512, (t % 65) * 128, (t / 65) * 256, 256, t / 65);
    } else {
        int t = bx - 266;
        gemm_dev<0, 0>(sA, sW, x, msg, Wq, bq, nullptr,
                       MTOT, 128, t * 128, 0, 128, 0);
    }
}

// KV projections fused (17 + 65 CTAs)
__global__ void __launch_bounds__(256, 2) kv_k(
    const float* __restrict__ x, const float* __restrict__ msg,
    const float* __restrict__ kv1w, const float* __restrict__ kv1b,
    const float* __restrict__ kv2w, const float* __restrict__ kv2b)
{
    __shared__ __align__(16) float sA[32 * AST];
    __shared__ __align__(16) float sW[32 * AST];
    int bx = blockIdx.x;
    if (bx < 17)
        gemm_dev<2, 0>(sA, sW, x, msg, kv1w, kv1b, nullptr, 2080, 128, bx * 128, 0, 128, 0);
    else
        gemm_dev<2, 1>(sA, sW, x, msg, kv2w, kv2b, nullptr, 8224, 128, (bx - 17) * 128, 0, 128, 0);
}

// Output projection
__global__ void __launch_bounds__(256, 2) out_k(
    const float* __restrict__ x, const float* __restrict__ msg,
    const float* __restrict__ pw, const float* __restrict__ pb,
    float* __restrict__ out)
{
    __shared__ __align__(16) float sA[32 * AST];
    __shared__ __align__(16) float sW[32 * AST];
    gemm_dev<3, 0>(sA, sW, x, msg, pw, pb, out, MTOT, 128, blockIdx.x * 128, 0, 128, 0);
}

// ---------------------------------------------------------------------------
// Split-K reduce + bias + LayerNorm + exact GELU -> g_xk  (both branches fused)
// ---------------------------------------------------------------------------
template <int BR>
__device__ __forceinline__ void sr_finish_dev(
    const float* __restrict__ bias, const float* __restrict__ lng,
    const float* __restrict__ lnb, int blk)
{
    constexpr int M  = BrCfg<BR>::M;
    constexpr int NS = BrCfg<BR>::NSPLIT;
    const float* part = BR ? g_p2 : g_p1;
    float* out        = BR ? g_xk2 : g_xk1;

    int warp  = threadIdx.x >> 5;
    int lanei = threadIdx.x & 31;
    int r = blk * 8 + warp;
    if (r >= M) return;

    float v[4];
    {
        float4 a = *(const float4*)(part + (size_t)r * 128 + lanei * 4);
        v[0] = a.x; v[1] = a.y; v[2] = a.z; v[3] = a.w;
    }
#pragma unroll
    for (int s = 1; s < NS; ++s) {
        float4 a = *(const float4*)(part + ((size_t)s * M + r) * 128 + lanei * 4);
        v[0] += a.x; v[1] += a.y; v[2] += a.z; v[3] += a.w;
    }
    {
        float4 bv = *(const float4*)(bias + lanei * 4);
        v[0] += bv.x; v[1] += bv.y; v[2] += bv.z; v[3] += bv.w;
    }
    float sum = v[0] + v[1] + v[2] + v[3];
    float sq  = v[0]*v[0] + v[1]*v[1] + v[2]*v[2] + v[3]*v[3];
#pragma unroll
    for (int ofs = 16; ofs >= 1; ofs >>= 1) {
        sum += __shfl_xor_sync(0xffffffffu, sum, ofs);
        sq  += __shfl_xor_sync(0xffffffffu, sq,  ofs);
    }
    float mean = sum * (1.f / 128.f);
    float var  = sq  * (1.f / 128.f) - mean * mean;
    float rstd = rsqrtf(var + 1e-5f);

    float4 gg = *(const float4*)(lng + lanei * 4);
    float4 bb = *(const float4*)(lnb + lanei * 4);
    float gv[4]  = {gg.x, gg.y, gg.z, gg.w};
    float bv2[4] = {bb.x, bb.y, bb.z, bb.w};
    float ov[4];
#pragma unroll
    for (int q2 = 0; q2 < 4; ++q2) {
        float t = (v[q2] - mean) * rstd * gv[q2] + bv2[q2];
        ov[q2] = 0.5f * t * (1.f + erff(t * 0.70710678118654752f));
    }
    *(float4*)(out + (size_t)r * 128 + lanei * 4) = make_float4(ov[0], ov[1], ov[2], ov[3]);
}

__global__ void finish_all(
    const float* __restrict__ b1, const float* __restrict__ g1, const float* __restrict__ lb1,
    const float* __restrict__ b2, const float* __restrict__ g2, const float* __restrict__ lb2)
{
    if (blockIdx.x < 260) sr_finish_dev<0>(b1, g1, lb1, blockIdx.x);
    else                  sr_finish_dev<1>(b2, g2, lb2, blockIdx.x - 260);
}

// ---------------------------------------------------------------------------
// V fix-up: spatial rows -> v + dwconv3x3(v) + lc_b ; msg rows -> 2*v (fused)
// ---------------------------------------------------------------------------
template <int BR>
__device__ __forceinline__ void lc_dev(const float* __restrict__ lw,
                                       const float* __restrict__ lb, int idx)
{
    constexpr int LM = BrCfg<BR>::LM, L = BrCfg<BR>::L, WR = BrCfg<BR>::WR;
    const float* vt = BR ? g_vt2 : g_vt1;
    float* vo       = BR ? g_v2  : g_v1;
    if (idx >= Bb * LM * 64) return;
    int ch   = idx & 63;
    int rest = idx >> 6;
    int l = rest % LM, b = rest / LM;
    float c = vt[idx];
    if (l >= L) { vo[idx] = 2.f * c; return; }
    int hr = l / WR, wr = l % WR;
    float a = lb[ch];
#pragma unroll
    for (int di = 0; di < 3; ++di)
#pragma unroll
        for (int dj = 0; dj < 3; ++dj) {
            int nh = hr + di - 1, nw = wr + dj - 1;
            if (nh >= 0 && nh < WR && nw >= 0 && nw < WR)
                a += vt[((size_t)(b * LM) + nh * WR + nw) * 64 + ch] * lw[ch * 9 + di * 3 + dj];
        }
    vo[idx] = c + a;
}

__global__ void lc_all(const float* __restrict__ w1, const float* __restrict__ b1,
                       const float* __restrict__ w2, const float* __restrict__ b2)
{
    int bx = blockIdx.x;
    if (bx < 520) lc_dev<0>(w1, b1, bx * 256 + threadIdx.x);
    else          lc_dev<1>(w2, b2, (bx - 520) * 256 + threadIdx.x);
}

// ---------------------------------------------------------------------------
// Flash attention (packed f32x2): 1 query/thread, 128 q/block, 32-row chunks.
// Both branches fused via blockIdx.z.
// ---------------------------------------------------------------------------
template <int BR>
__device__ __forceinline__ void attn_dev(float* Ks, float* Vs)
{
    constexpr int LM   = BrCfg<BR>::LM;
    constexpr int QOFS = BR ? 64 : 0;
    constexpr float SCALE = 0.17677669529663687f;
    const float* gk = BR ? g_k2 : g_k1;
    const float* gv = BR ? g_v2 : g_v1;

    const int b   = blockIdx.y >> 1;
    const int h   = blockIdx.y & 1;
    const int tid = threadIdx.x;
    const int qrow = blockIdx.x * 128 + tid;
    const bool qv  = qrow < NTOT;
    const int  qr  = qv ? qrow : NTOT - 1;

    ull q2[16];
    {
        const ulonglong2* qp = (const ulonglong2*)(g_q + (size_t)(b * NTOT + qr) * 128 + QOFS + h * 32);
#pragma unroll
        for (int i = 0; i < 8; ++i) {
            ulonglong2 t = qp[i];
            q2[2 * i] = t.x; q2[2 * i + 1] = t.y;
        }
    }
    ull o2[16];
#pragma unroll
    for (int i = 0; i < 16; ++i) o2[i] = 0ull;
    float mrun = -1e30f, lsum = 0.f;

    const int lane = tid & 7, r8 = tid >> 3;

    for (int c0 = 0; c0 < LM; c0 += 32) {
        __syncthreads();
#pragma unroll
        for (int ps = 0; ps < 2; ++ps) {
            int kr = ps * 16 + r8;
            int src = c0 + kr;
            float4 kk4 = make_float4(0.f, 0.f, 0.f, 0.f);
            float4 vv4 = make_float4(0.f, 0.f, 0.f, 0.f);
            if (src < LM) {
                size_t base = (size_t)(b * LM + src) * 64 + h * 32 + lane * 4;
                kk4 = *(const float4*)(gk + base);
                vv4 = *(const float4*)(gv + base);
            }
            *(float4*)(Ks + kr * 32 + lane * 4) = kk4;
            *(float4*)(Vs + kr * 32 + lane * 4) = vv4;
        }
        __syncthreads();

        const int lim = LM - c0;
        float s[32];
#pragma unroll 4
        for (int kk = 0; kk < 32; ++kk) {
            const ulonglong2* kp = (const ulonglong2*)(Ks + kk * 32);
            ull d0 = 0ull, d1 = 0ull;
#pragma unroll
            for (int e = 0; e < 8; ++e) {
                ulonglong2 t = kp[e];
                d0 = ffma2(q2[2 * e],     t.x, d0);
                d1 = ffma2(q2[2 * e + 1], t.y, d1);
            }
            float2 fa = unpack2(d0), fb = unpack2(d1);
            float d = (fa.x + fa.y) + (fb.x + fb.y);
            s[kk] = (kk < lim) ? d * SCALE : -1e30f;
        }
        float mloc = s[0];
#pragma unroll
        for (int kk = 1; kk < 32; ++kk) mloc = fmaxf(mloc, s[kk]);
        float mnew = fmaxf(mrun, mloc);
        float corr = __expf(mrun - mnew);
        lsum *= corr;
        ull corr2 = pack2(corr);
#pragma unroll
        for (int i = 0; i < 16; ++i) o2[i] = fmul2(o2[i], corr2);
        float ls = 0.f;
#pragma unroll
        for (int kk = 0; kk < 32; ++kk) {
            float p = __expf(s[kk] - mnew);
            s[kk] = p;
            ls += p;
        }
        lsum += ls;
#pragma unroll 4
        for (int kk = 0; kk < 32; ++kk) {
            ull p2 = pack2(s[kk]);
            const ulonglong2* vp = (const ulonglong2*)(Vs + kk * 32);
#pragma unroll
            for (int e = 0; e < 8; ++e) {
                ulonglong2 t = vp[e];
                o2[2 * e]     = ffma2(p2, t.x, o2[2 * e]);
                o2[2 * e + 1] = ffma2(p2, t.y, o2[2 * e + 1]);
            }
        }
        mrun = mnew;
    }

    if (qv) {
        ull inv2 = pack2(1.f / lsum);
        ulonglong2* op = (ulonglong2*)(g_cat + (size_t)(b * NTOT + qrow) * 128 + QOFS + h * 32);
#pragma unroll
        for (int i = 0; i < 8; ++i)
            op[i] = make_ulonglong2(fmul2(o2[2 * i], inv2), fmul2(o2[2 * i + 1], inv2));
    }
}

__global__ void __launch_bounds__(128) attn_all()
{
    __shared__ __align__(16) float Ks[32 * 32];
    __shared__ __align__(16) float Vs[32 * 32];
    if (blockIdx.z == 0) attn_dev<0>(Ks, Vs);
    else                 attn_dev<1>(Ks, Vs);
}

// ---------------------------------------------------------------------------
// Launch
// ---------------------------------------------------------------------------
extern "C" void kernel_launch(void* const* d_in, const int* in_sizes, int n_in,
                              void* d_out, int out_size)
{
    (void)in_sizes; (void)n_in; (void)out_size;
    const float* x     = (const float*)d_in[0];
    const float* msg   = (const float*)d_in[1];
    const float* Wq    = (const float*)d_in[2];
    const float* bq    = (const float*)d_in[3];
    const float* sr1w  = (const float*)d_in[4];
    const float* sr1b  = (const float*)d_in[5];
    const float* ln1g  = (const float*)d_in[6];
    const float* ln1b  = (const float*)d_in[7];
    const float* sr2w  = (const float*)d_in[8];
    const float* sr2b  = (const float*)d_in[9];
    const float* ln2g  = (const float*)d_in[10];
    const float* ln2b  = (const float*)d_in[11];
    const float* kv1w  = (const float*)d_in[12];
    const float* kv1b  = (const float*)d_in[13];
    const float* kv2w  = (const float*)d_in[14];
    const float* kv2b  = (const float*)d_in[15];
    const float* lc1w  = (const float*)d_in[16];
    const float* lc1b  = (const float*)d_in[17];
    const float* lc2w  = (const float*)d_in[18];
    const float* lc2b  = (const float*)d_in[19];
    const float* projw = (const float*)d_in[20];
    const float* projb = (const float*)d_in[21];
    float* out = (float*)d_out;

    // SR conv weight repack (both)
    repack_all<<<1280, 256>>>(sr1w, sr2w);

    // Fused: SR1 split-K + SR2 split-K + Q projection
    phase1_k<<<523, 256>>>(x, msg, Wq, bq);

    // Fused reduce + bias + LN + GELU
    finish_all<<<1288, 256>>>(sr1b, ln1g, ln1b, sr2b, ln2g, ln2b);

    // Fused KV projections
    kv_k<<<82, 256>>>(x, msg, kv1w, kv1b, kv2w, kv2b);

    // Fused depthwise 3x3 V fix-up
    lc_all<<<2576, 256>>>(lc1w, lc1b, lc2w, lc2b);

    // Fused flash attention (both branches)
    attn_all<<<dim3(33, 16, 2), 128>>>();

    // Output projection + residual + split store
    out_k<<<257, 256>>>(x, msg, projw, projb, out);
}

// round 6
// speedup vs baseline: 1.3918x; 1.1946x over previous
#include <cuda_runtime.h>
#include <math.h>

typedef unsigned long long ull;

// ---------------------------------------------------------------------------
// Packed f32x2 helpers (attention path)
// ---------------------------------------------------------------------------
__device__ __forceinline__ ull ffma2(ull a, ull b, ull c) {
    ull d;
    asm("fma.rn.f32x2 %0, %1, %2, %3;" : "=l"(d) : "l"(a), "l"(b), "l"(c));
    return d;
}
__device__ __forceinline__ ull fmul2(ull a, ull b) {
    ull d;
    asm("mul.rn.f32x2 %0, %1, %2;" : "=l"(d) : "l"(a), "l"(b));
    return d;
}
__device__ __forceinline__ ull pack2(float x) {
    ull r; unsigned u = __float_as_uint(x);
    asm("mov.b64 %0, {%1, %1};" : "=l"(r) : "r"(u));
    return r;
}
__device__ __forceinline__ float2 unpack2(ull v) {
    float2 r;
    asm("mov.b64 {%0, %1}, %2;" : "=f"(r.x), "=f"(r.y) : "l"(v));
    return r;
}

// tf32 helpers (GEMM path)
__device__ __forceinline__ float to_tf32(float f) {
    unsigned r;
    asm("cvt.rna.tf32.f32 %0, %1;" : "=r"(r) : "f"(f));
    return __uint_as_float(r);
}
__device__ __forceinline__ void mma_tf32(float* c, const unsigned* a, unsigned b0, unsigned b1) {
    asm volatile(
        "mma.sync.aligned.m16n8k8.row.col.f32.tf32.tf32.f32 "
        "{%0,%1,%2,%3},{%4,%5,%6,%7},{%8,%9},{%0,%1,%2,%3};"
        : "+f"(c[0]), "+f"(c[1]), "+f"(c[2]), "+f"(c[3])
        : "r"(a[0]), "r"(a[1]), "r"(a[2]), "r"(a[3]), "r"(b0), "r"(b1));
}

// ---------------------------------------------------------------------------
// Problem constants
// ---------------------------------------------------------------------------
constexpr int Bb   = 8;
constexpr int Cc   = 128;
constexpr int N0   = 4096;
constexpr int MSGN = 4;
constexpr int NTOT = N0 + MSGN;  // 4100
constexpr int Wimg = 64;
constexpr int MTOT = Bb * NTOT;  // 32800
constexpr size_t OUT2_OFS = (size_t)Bb * N0 * Cc;
constexpr int AST = 132;

template <int BR> struct BrCfg;
template <> struct BrCfg<0> {
    static constexpr int S = 4, WR = 16, L = 256, LM = 260, K = 2048, NSPLIT = 8, M = Bb * 260;
};
template <> struct BrCfg<1> {
    static constexpr int S = 2, WR = 32, L = 1024, LM = 1028, K = 512, NSPLIT = 2, M = Bb * 1028;
};

// ---------------------------------------------------------------------------
// Scratch (device globals — no allocation allowed)
// ---------------------------------------------------------------------------
__device__ float g_q  [MTOT * Cc];
__device__ float g_cat[MTOT * Cc];
__device__ float g_w1r[128 * 2048];
__device__ float g_w2r[128 * 512];
__device__ float g_p1 [8 * 2080 * 128];
__device__ float g_p2 [2 * 8224 * 128];
__device__ float g_xk1[2080 * 128];
__device__ float g_xk2[8224 * 128];
__device__ float g_k1 [2080 * 64];
__device__ float g_vt1[2080 * 64];
__device__ float g_v1 [2080 * 64];
__device__ float g_k2 [8224 * 64];
__device__ float g_vt2[8224 * 64];
__device__ float g_v2 [8224 * 64];

// ---------------------------------------------------------------------------
// Weight repack (both SR convs): sr_w[o][c][p] -> wr[o][p*128 + c]
// ---------------------------------------------------------------------------
__global__ void repack_all(const float* __restrict__ s1, const float* __restrict__ s2) {
    int idx = blockIdx.x * 256 + threadIdx.x;
    constexpr int T1 = 128 * 16 * 128;
    constexpr int T2 = 128 * 4  * 128;
    if (idx < T1) {
        int o = idx / (16 * 128);
        int rem = idx % (16 * 128);
        int p = rem / 128, c = rem % 128;
        g_w1r[idx] = s1[(o * 128 + c) * 16 + p];
    } else if (idx < T1 + T2) {
        int j = idx - T1;
        int o = j / (4 * 128);
        int rem = j % (4 * 128);
        int p = rem / 128, c = rem % 128;
        g_w2r[j] = s2[(o * 128 + c) * 4 + p];
    }
}

// ---------------------------------------------------------------------------
// tf32 tensor-core tiled GEMM: C[M,128] = A[M,K] @ W[128,K]^T
//  MODE 0: Q proj -> g_q (+bias)        MODE 1: SR split-K partials -> g_p
//  MODE 2: KV proj -> g_k/g_vt (+bias)  MODE 3: out proj -> d_out (+bias+res)
// 128x128x32 tile, 256 thr = 8 warps (4 M x 2 N), warp tile 32x64,
// mma.sync m16n8k8 tf32, fp32 accumulate. Inputs rounded to tf32 at staging.
// ---------------------------------------------------------------------------
template <int MODE, int BR>
__device__ __forceinline__ void gemm_dev(
    float* sA, float* sW,
    const float* __restrict__ x, const float* __restrict__ msg,
    const float* __restrict__ Wext, const float* __restrict__ bias,
    float* __restrict__ outext,
    int M, int Ktot, int tileM, int kb, int Ks, int splitIdx)
{
    const int tid = threadIdx.x;
    const float* Wp = (MODE == 1) ? (BR ? g_w2r : g_w1r) : Wext;

    const int lane = tid & 7;   // 8 lanes * float4 = 32 K-values (staging)
    const int rq   = tid >> 3;  // 0..31 (staging)

    const float* abase[4];
    bool avalid[4], aspat[4];
#pragma unroll
    for (int ps = 0; ps < 4; ++ps) {
        int grow = tileM + ps * 32 + rq;
        bool val = grow < M;
        avalid[ps] = val;
        aspat[ps]  = true;
        int g2 = val ? grow : 0;
        if (MODE == 0) {
            int b = g2 / NTOT, n = g2 % NTOT;
            abase[ps] = (n < N0)
                ? x   + (size_t)(b * N0   + n)        * 128 + lane * 4
                : msg + (size_t)(b * MSGN + (n - N0)) * 128 + lane * 4;
        } else if (MODE == 2) {
            const float* A = BR ? g_xk2 : g_xk1;
            abase[ps] = A + (size_t)g2 * 128 + lane * 4;
        } else if (MODE == 3) {
            abase[ps] = g_cat + (size_t)g2 * 128 + lane * 4;
        } else {  // MODE 1: SR patch gather
            constexpr int LMc = BrCfg<BR>::LM, Lc = BrCfg<BR>::L;
            constexpr int WRc = BrCfg<BR>::WR, Sc = BrCfg<BR>::S;
            int b = g2 / LMc, l = g2 % LMc;
            if (l < Lc) {
                int hr = l / WRc, wr = l % WRc;
                abase[ps] = x + (size_t)(b * N0 + (hr * Sc) * Wimg + wr * Sc) * 128 + lane * 4;
            } else {
                abase[ps] = msg + (size_t)(b * MSGN + (l - Lc)) * 128 + lane * 4;
                aspat[ps] = false;
            }
        }
    }

    // mma coordinates
    const int warp   = tid >> 5;
    const int lane31 = tid & 31;
    const int warp_m = warp >> 1;     // 0..3 -> M offset warp_m*32
    const int warp_n = warp & 1;      // 0..1 -> N offset warp_n*64
    const int gid    = lane31 >> 2;   // 0..7
    const int tig    = lane31 & 3;    // 0..3

    float acc[2][8][4];
#pragma unroll
    for (int mt = 0; mt < 2; ++mt)
#pragma unroll
        for (int nt = 0; nt < 8; ++nt)
#pragma unroll
            for (int q = 0; q < 4; ++q) acc[mt][nt][q] = 0.f;

    for (int k0 = kb; k0 < kb + Ks; k0 += 32) {
        // W tile -> sW[k][n]  (tf32-rounded)
#pragma unroll
        for (int ps = 0; ps < 4; ++ps) {
            int n = ps * 32 + rq;
            float4 w = *(const float4*)(Wp + (size_t)n * Ktot + k0 + lane * 4);
            sW[(lane * 4 + 0) * AST + n] = to_tf32(w.x);
            sW[(lane * 4 + 1) * AST + n] = to_tf32(w.y);
            sW[(lane * 4 + 2) * AST + n] = to_tf32(w.z);
            sW[(lane * 4 + 3) * AST + n] = to_tf32(w.w);
        }
        // A tile -> sA[k][m]  (tf32-rounded)
        int aofs_s = k0, aofs_m = k0;
        if (MODE == 1) {
            constexpr int Sc = BrCfg<BR>::S;
            int p = k0 >> 7, c0 = k0 & 127;
            aofs_s = ((p / Sc) * Wimg + (p % Sc)) * 128 + c0;
            aofs_m = c0;
        }
#pragma unroll
        for (int ps = 0; ps < 4; ++ps) {
            int row = ps * 32 + rq;
            float4 a = make_float4(0.f, 0.f, 0.f, 0.f);
            if (avalid[ps])
                a = *(const float4*)(abase[ps] + (aspat[ps] ? aofs_s : aofs_m));
            sA[(lane * 4 + 0) * AST + row] = to_tf32(a.x);
            sA[(lane * 4 + 1) * AST + row] = to_tf32(a.y);
            sA[(lane * 4 + 2) * AST + row] = to_tf32(a.z);
            sA[(lane * 4 + 3) * AST + row] = to_tf32(a.w);
        }
        __syncthreads();

        // 4 k-steps of 8; per k-step: 2 A frags, 8 B frags, 16 HMMA
#pragma unroll
        for (int ks = 0; ks < 4; ++ks) {
            const int kr0 = ks * 8 + tig;       // k rows tig and tig+4
            unsigned afr[2][4];
#pragma unroll
            for (int mt = 0; mt < 2; ++mt) {
                int m = warp_m * 32 + mt * 16 + gid;
                afr[mt][0] = __float_as_uint(sA[kr0 * AST + m]);
                afr[mt][1] = __float_as_uint(sA[kr0 * AST + m + 8]);
                afr[mt][2] = __float_as_uint(sA[(kr0 + 4) * AST + m]);
                afr[mt][3] = __float_as_uint(sA[(kr0 + 4) * AST + m + 8]);
            }
#pragma unroll
            for (int nt = 0; nt < 8; ++nt) {
                int n = warp_n * 64 + nt * 8 + gid;
                unsigned b0 = __float_as_uint(sW[kr0 * AST + n]);
                unsigned b1 = __float_as_uint(sW[(kr0 + 4) * AST + n]);
                mma_tf32(acc[0][nt], afr[0], b0, b1);
                mma_tf32(acc[1][nt], afr[1], b0, b1);
            }
        }
        __syncthreads();
    }

    // ---- epilogue ----
    float bs[8][2];
    if (MODE != 1) {
#pragma unroll
        for (int nt = 0; nt < 8; ++nt) {
            int cn = warp_n * 64 + nt * 8 + 2 * tig;
            bs[nt][0] = bias[cn];
            bs[nt][1] = bias[cn + 1];
        }
    }

#pragma unroll
    for (int mt = 0; mt < 2; ++mt)
#pragma unroll
    for (int half = 0; half < 2; ++half) {
        int r = tileM + warp_m * 32 + mt * 16 + half * 8 + gid;
        if (r >= M) continue;
        if (MODE == 0) {
            float* o = g_q + (size_t)r * 128;
#pragma unroll
            for (int nt = 0; nt < 8; ++nt) {
                int cn = warp_n * 64 + nt * 8 + 2 * tig;
                *(float2*)(o + cn) = make_float2(acc[mt][nt][half * 2]     + bs[nt][0],
                                                 acc[mt][nt][half * 2 + 1] + bs[nt][1]);
            }
        } else if (MODE == 1) {
            float* o = (BR ? g_p2 : g_p1) + ((size_t)splitIdx * M + r) * 128;
#pragma unroll
            for (int nt = 0; nt < 8; ++nt) {
                int cn = warp_n * 64 + nt * 8 + 2 * tig;
                *(float2*)(o + cn) = make_float2(acc[mt][nt][half * 2],
                                                 acc[mt][nt][half * 2 + 1]);
            }
        } else if (MODE == 2) {
            float* ok = (BR ? g_k2  : g_k1 ) + (size_t)r * 64;
            float* ov = (BR ? g_vt2 : g_vt1) + (size_t)r * 64;
#pragma unroll
            for (int nt = 0; nt < 8; ++nt) {
                int cn = warp_n * 64 + nt * 8 + 2 * tig;
                float2 v = make_float2(acc[mt][nt][half * 2]     + bs[nt][0],
                                       acc[mt][nt][half * 2 + 1] + bs[nt][1]);
                if (cn < 64) *(float2*)(ok + cn)      = v;
                else         *(float2*)(ov + cn - 64) = v;
            }
        } else {  // MODE 3
            int b = r / NTOT, n = r % NTOT;
            const float* res;
            float* o;
            if (n < N0) {
                res = x      + (size_t)(b * N0 + n) * 128;
                o   = outext + (size_t)(b * N0 + n) * 128;
            } else {
                res = msg    + (size_t)(b * MSGN + (n - N0)) * 128;
                o   = outext + OUT2_OFS + (size_t)(b * MSGN + (n - N0)) * 128;
            }
#pragma unroll
            for (int nt = 0; nt < 8; ++nt) {
                int cn = warp_n * 64 + nt * 8 + 2 * tig;
                float2 rv = *(const float2*)(res + cn);
                *(float2*)(o + cn) = make_float2(acc[mt][nt][half * 2]     + bs[nt][0] + rv.x,
                                                 acc[mt][nt][half * 2 + 1] + bs[nt][1] + rv.y);
            }
        }
    }
}

// ---------------------------------------------------------------------------
// Phase-1 fused: SR1 split-K (136) + SR2 split-K (130) + Qproj (257)
// ---------------------------------------------------------------------------
__global__ void __launch_bounds__(256, 2) phase1_k(
    const float* __restrict__ x, const float* __restrict__ msg,
    const float* __restrict__ Wq, const float* __restrict__ bq)
{
    __shared__ __align__(16) float sA[32 * AST];
    __shared__ __align__(16) float sW[32 * AST];
    int bx = blockIdx.x;
    if (bx < 136) {
        gemm_dev<1, 0>(sA, sW, x, msg, nullptr, nullptr, nullptr,
                       2080, 2048, (bx % 17) * 128, (bx / 17) * 256, 256, bx / 17);
    } else if (bx < 266) {
        int t = bx - 136;
        gemm_dev<1, 1>(sA, sW, x, msg, nullptr, nullptr, nullptr,
                       8224, 512, (t % 65) * 128, (t / 65) * 256, 256, t / 65);
    } else {
        int t = bx - 266;
        gemm_dev<0, 0>(sA, sW, x, msg, Wq, bq, nullptr,
                       MTOT, 128, t * 128, 0, 128, 0);
    }
}

// KV projections fused (17 + 65 CTAs)
__global__ void __launch_bounds__(256, 2) kv_k(
    const float* __restrict__ x, const float* __restrict__ msg,
    const float* __restrict__ kv1w, const float* __restrict__ kv1b,
    const float* __restrict__ kv2w, const float* __restrict__ kv2b)
{
    __shared__ __align__(16) float sA[32 * AST];
    __shared__ __align__(16) float sW[32 * AST];
    int bx = blockIdx.x;
    if (bx < 17)
        gemm_dev<2, 0>(sA, sW, x, msg, kv1w, kv1b, nullptr, 2080, 128, bx * 128, 0, 128, 0);
    else
        gemm_dev<2, 1>(sA, sW, x, msg, kv2w, kv2b, nullptr, 8224, 128, (bx - 17) * 128, 0, 128, 0);
}

// Output projection
__global__ void __launch_bounds__(256, 2) out_k(
    const float* __restrict__ x, const float* __restrict__ msg,
    const float* __restrict__ pw, const float* __restrict__ pb,
    float* __restrict__ out)
{
    __shared__ __align__(16) float sA[32 * AST];
    __shared__ __align__(16) float sW[32 * AST];
    gemm_dev<3, 0>(sA, sW, x, msg, pw, pb, out, MTOT, 128, blockIdx.x * 128, 0, 128, 0);
}

// ---------------------------------------------------------------------------
// Split-K reduce + bias + LayerNorm + exact GELU -> g_xk (both branches fused)
// ---------------------------------------------------------------------------
template <int BR>
__device__ __forceinline__ void sr_finish_dev(
    const float* __restrict__ bias, const float* __restrict__ lng,
    const float* __restrict__ lnb, int blk)
{
    constexpr int M  = BrCfg<BR>::M;
    constexpr int NS = BrCfg<BR>::NSPLIT;
    const float* part = BR ? g_p2 : g_p1;
    float* out        = BR ? g_xk2 : g_xk1;

    int warp  = threadIdx.x >> 5;
    int lanei = threadIdx.x & 31;
    int r = blk * 8 + warp;
    if (r >= M) return;

    float v[4];
    {
        float4 a = *(const float4*)(part + (size_t)r * 128 + lanei * 4);
        v[0] = a.x; v[1] = a.y; v[2] = a.z; v[3] = a.w;
    }
#pragma unroll
    for (int s = 1; s < NS; ++s) {
        float4 a = *(const float4*)(part + ((size_t)s * M + r) * 128 + lanei * 4);
        v[0] += a.x; v[1] += a.y; v[2] += a.z; v[3] += a.w;
    }
    {
        float4 bv = *(const float4*)(bias + lanei * 4);
        v[0] += bv.x; v[1] += bv.y; v[2] += bv.z; v[3] += bv.w;
    }
    float sum = v[0] + v[1] + v[2] + v[3];
    float sq  = v[0]*v[0] + v[1]*v[1] + v[2]*v[2] + v[3]*v[3];
#pragma unroll
    for (int ofs = 16; ofs >= 1; ofs >>= 1) {
        sum += __shfl_xor_sync(0xffffffffu, sum, ofs);
        sq  += __shfl_xor_sync(0xffffffffu, sq,  ofs);
    }
    float mean = sum * (1.f / 128.f);
    float var  = sq  * (1.f / 128.f) - mean * mean;
    float rstd = rsqrtf(var + 1e-5f);

    float4 gg = *(const float4*)(lng + lanei * 4);
    float4 bb = *(const float4*)(lnb + lanei * 4);
    float gv[4]  = {gg.x, gg.y, gg.z, gg.w};
    float bv2[4] = {bb.x, bb.y, bb.z, bb.w};
    float ov[4];
#pragma unroll
    for (int q2 = 0; q2 < 4; ++q2) {
        float t = (v[q2] - mean) * rstd * gv[q2] + bv2[q2];
        ov[q2] = 0.5f * t * (1.f + erff(t * 0.70710678118654752f));
    }
    *(float4*)(out + (size_t)r * 128 + lanei * 4) = make_float4(ov[0], ov[1], ov[2], ov[3]);
}

__global__ void finish_all(
    const float* __restrict__ b1, const float* __restrict__ g1, const float* __restrict__ lb1,
    const float* __restrict__ b2, const float* __restrict__ g2, const float* __restrict__ lb2)
{
    if (blockIdx.x < 260) sr_finish_dev<0>(b1, g1, lb1, blockIdx.x);
    else                  sr_finish_dev<1>(b2, g2, lb2, blockIdx.x - 260);
}

// ---------------------------------------------------------------------------
// V fix-up: spatial rows -> v + dwconv3x3(v) + lc_b ; msg rows -> 2*v (fused)
// ---------------------------------------------------------------------------
template <int BR>
__device__ __forceinline__ void lc_dev(const float* __restrict__ lw,
                                       const float* __restrict__ lb, int idx)
{
    constexpr int LM = BrCfg<BR>::LM, L = BrCfg<BR>::L, WR = BrCfg<BR>::WR;
    const float* vt = BR ? g_vt2 : g_vt1;
    float* vo       = BR ? g_v2  : g_v1;
    if (idx >= Bb * LM * 64) return;
    int ch   = idx & 63;
    int rest = idx >> 6;
    int l = rest % LM, b = rest / LM;
    float c = vt[idx];
    if (l >= L) { vo[idx] = 2.f * c; return; }
    int hr = l / WR, wr = l % WR;
    float a = lb[ch];
#pragma unroll
    for (int di = 0; di < 3; ++di)
#pragma unroll
        for (int dj = 0; dj < 3; ++dj) {
            int nh = hr + di - 1, nw = wr + dj - 1;
            if (nh >= 0 && nh < WR && nw >= 0 && nw < WR)
                a += vt[((size_t)(b * LM) + nh * WR + nw) * 64 + ch] * lw[ch * 9 + di * 3 + dj];
        }
    vo[idx] = c + a;
}

__global__ void lc_all(const float* __restrict__ w1, const float* __restrict__ b1,
                       const float* __restrict__ w2, const float* __restrict__ b2)
{
    int bx = blockIdx.x;
    if (bx < 520) lc_dev<0>(w1, b1, bx * 256 + threadIdx.x);
    else          lc_dev<1>(w2, b2, (bx - 520) * 256 + threadIdx.x);
}

// ---------------------------------------------------------------------------
// Flash attention (packed f32x2): 1 query/thread, 128 q/block, 32-row chunks.
// ---------------------------------------------------------------------------
template <int BR>
__device__ __forceinline__ void attn_dev(float* Ks, float* Vs)
{
    constexpr int LM   = BrCfg<BR>::LM;
    constexpr int QOFS = BR ? 64 : 0;
    constexpr float SCALE = 0.17677669529663687f;
    const float* gk = BR ? g_k2 : g_k1;
    const float* gv = BR ? g_v2 : g_v1;

    const int b   = blockIdx.y >> 1;
    const int h   = blockIdx.y & 1;
    const int tid = threadIdx.x;
    const int qrow = blockIdx.x * 128 + tid;
    const bool qv  = qrow < NTOT;
    const int  qr  = qv ? qrow : NTOT - 1;

    ull q2[16];
    {
        const ulonglong2* qp = (const ulonglong2*)(g_q + (size_t)(b * NTOT + qr) * 128 + QOFS + h * 32);
#pragma unroll
        for (int i = 0; i < 8; ++i) {
            ulonglong2 t = qp[i];
            q2[2 * i] = t.x; q2[2 * i + 1] = t.y;
        }
    }
    ull o2[16];
#pragma unroll
    for (int i = 0; i < 16; ++i) o2[i] = 0ull;
    float mrun = -1e30f, lsum = 0.f;

    const int lane = tid & 7, r8 = tid >> 3;

    for (int c0 = 0; c0 < LM; c0 += 32) {
        __syncthreads();
#pragma unroll
        for (int ps = 0; ps < 2; ++ps) {
            int kr = ps * 16 + r8;
            int src = c0 + kr;
            float4 kk4 = make_float4(0.f, 0.f, 0.f, 0.f);
            float4 vv4 = make_float4(0.f, 0.f, 0.f, 0.f);
            if (src < LM) {
                size_t base = (size_t)(b * LM + src) * 64 + h * 32 + lane * 4;
                kk4 = *(const float4*)(gk + base);
                vv4 = *(const float4*)(gv + base);
            }
            *(float4*)(Ks + kr * 32 + lane * 4) = kk4;
            *(float4*)(Vs + kr * 32 + lane * 4) = vv4;
        }
        __syncthreads();

        const int lim = LM - c0;
        float s[32];
#pragma unroll 4
        for (int kk = 0; kk < 32; ++kk) {
            const ulonglong2* kp = (const ulonglong2*)(Ks + kk * 32);
            ull d0 = 0ull, d1 = 0ull;
#pragma unroll
            for (int e = 0; e < 8; ++e) {
                ulonglong2 t = kp[e];
                d0 = ffma2(q2[2 * e],     t.x, d0);
                d1 = ffma2(q2[2 * e + 1], t.y, d1);
            }
            float2 fa = unpack2(d0), fb = unpack2(d1);
            float d = (fa.x + fa.y) + (fb.x + fb.y);
            s[kk] = (kk < lim) ? d * SCALE : -1e30f;
        }
        float mloc = s[0];
#pragma unroll
        for (int kk = 1; kk < 32; ++kk) mloc = fmaxf(mloc, s[kk]);
        float mnew = fmaxf(mrun, mloc);
        float corr = __expf(mrun - mnew);
        lsum *= corr;
        ull corr2 = pack2(corr);
#pragma unroll
        for (int i = 0; i < 16; ++i) o2[i] = fmul2(o2[i], corr2);
        float ls = 0.f;
#pragma unroll
        for (int kk = 0; kk < 32; ++kk) {
            float p = __expf(s[kk] - mnew);
            s[kk] = p;
            ls += p;
        }
        lsum += ls;
#pragma unroll 4
        for (int kk = 0; kk < 32; ++kk) {
            ull p2 = pack2(s[kk]);
            const ulonglong2* vp = (const ulonglong2*)(Vs + kk * 32);
#pragma unroll
            for (int e = 0; e < 8; ++e) {
                ulonglong2 t = vp[e];
                o2[2 * e]     = ffma2(p2, t.x, o2[2 * e]);
                o2[2 * e + 1] = ffma2(p2, t.y, o2[2 * e + 1]);
            }
        }
        mrun = mnew;
    }

    if (qv) {
        ull inv2 = pack2(1.f / lsum);
        ulonglong2* op = (ulonglong2*)(g_cat + (size_t)(b * NTOT + qrow) * 128 + QOFS + h * 32);
#pragma unroll
        for (int i = 0; i < 8; ++i)
            op[i] = make_ulonglong2(fmul2(o2[2 * i], inv2), fmul2(o2[2 * i + 1], inv2));
    }
}

__global__ void __launch_bounds__(128) attn_all()
{
    __shared__ __align__(16) float Ks[32 * 32];
    __shared__ __align__(16) float Vs[32 * 32];
    if (blockIdx.z == 0) attn_dev<0>(Ks, Vs);
    else                 attn_dev<1>(Ks, Vs);
}

// ---------------------------------------------------------------------------
// Launch
// ---------------------------------------------------------------------------
extern "C" void kernel_launch(void* const* d_in, const int* in_sizes, int n_in,
                              void* d_out, int out_size)
{
    (void)in_sizes; (void)n_in; (void)out_size;
    const float* x     = (const float*)d_in[0];
    const float* msg   = (const float*)d_in[1];
    const float* Wq    = (const float*)d_in[2];
    const float* bq    = (const float*)d_in[3];
    const float* sr1w  = (const float*)d_in[4];
    const float* sr1b  = (const float*)d_in[5];
    const float* ln1g  = (const float*)d_in[6];
    const float* ln1b  = (const float*)d_in[7];
    const float* sr2w  = (const float*)d_in[8];
    const float* sr2b  = (const float*)d_in[9];
    const float* ln2g  = (const float*)d_in[10];
    const float* ln2b  = (const float*)d_in[11];
    const float* kv1w  = (const float*)d_in[12];
    const float* kv1b  = (const float*)d_in[13];
    const float* kv2w  = (const float*)d_in[14];
    const float* kv2b  = (const float*)d_in[15];
    const float* lc1w  = (const float*)d_in[16];
    const float* lc1b  = (const float*)d_in[17];
    const float* lc2w  = (const float*)d_in[18];
    const float* lc2b  = (const float*)d_in[19];
    const float* projw = (const float*)d_in[20];
    const float* projb = (const float*)d_in[21];
    float* out = (float*)d_out;

    // SR conv weight repack (both)
    repack_all<<<1280, 256>>>(sr1w, sr2w);

    // Fused: SR1 split-K + SR2 split-K + Q projection (tf32 mma)
    phase1_k<<<523, 256>>>(x, msg, Wq, bq);

    // Fused reduce + bias + LN + GELU
    finish_all<<<1288, 256>>>(sr1b, ln1g, ln1b, sr2b, ln2g, ln2b);

    // Fused KV projections (tf32 mma)
    kv_k<<<82, 256>>>(x, msg, kv1w, kv1b, kv2w, kv2b);

    // Fused depthwise 3x3 V fix-up
    lc_all<<<2576, 256>>>(lc1w, lc1b, lc2w, lc2b);

    // Fused flash attention (both branches)
    attn_all<<<dim3(33, 16, 2), 128>>>();

    // Output projection + residual + split store (tf32 mma)
    out_k<<<257, 256>>>(x, msg, projw, projb, out);
}

// round 7
// speedup vs baseline: 1.9380x; 1.3924x over previous
#include <cuda_runtime.h>
#include <math.h>

typedef unsigned long long ull;

// ---------------------------------------------------------------------------
// tf32 helpers
// ---------------------------------------------------------------------------
__device__ __forceinline__ float to_tf32(float f) {
    unsigned r;
    asm("cvt.rna.tf32.f32 %0, %1;" : "=r"(r) : "f"(f));
    return __uint_as_float(r);
}
__device__ __forceinline__ void mma_tf32(float* c, const unsigned* a, unsigned b0, unsigned b1) {
    asm volatile(
        "mma.sync.aligned.m16n8k8.row.col.f32.tf32.tf32.f32 "
        "{%0,%1,%2,%3},{%4,%5,%6,%7},{%8,%9},{%0,%1,%2,%3};"
        : "+f"(c[0]), "+f"(c[1]), "+f"(c[2]), "+f"(c[3])
        : "r"(a[0]), "r"(a[1]), "r"(a[2]), "r"(a[3]), "r"(b0), "r"(b1));
}

// ---------------------------------------------------------------------------
// Problem constants
// ---------------------------------------------------------------------------
constexpr int Bb   = 8;
constexpr int Cc   = 128;
constexpr int N0   = 4096;
constexpr int MSGN = 4;
constexpr int NTOT = N0 + MSGN;  // 4100
constexpr int Wimg = 64;
constexpr int MTOT = Bb * NTOT;  // 32800
constexpr size_t OUT2_OFS = (size_t)Bb * N0 * Cc;
constexpr int AST = 132;

template <int BR> struct BrCfg;
template <> struct BrCfg<0> {
    static constexpr int S = 4, WR = 16, L = 256, LM = 260, K = 2048, NSPLIT = 8, M = Bb * 260;
};
template <> struct BrCfg<1> {
    static constexpr int S = 2, WR = 32, L = 1024, LM = 1028, K = 512, NSPLIT = 2, M = Bb * 1028;
};

// ---------------------------------------------------------------------------
// Scratch (device globals — no allocation allowed)
// ---------------------------------------------------------------------------
__device__ float g_q  [MTOT * Cc];
__device__ float g_cat[MTOT * Cc];
__device__ float g_w1r[128 * 2048];
__device__ float g_w2r[128 * 512];
__device__ float g_p1 [8 * 2080 * 128];
__device__ float g_p2 [2 * 8224 * 128];
__device__ float g_xk1[2080 * 128];
__device__ float g_xk2[8224 * 128];
__device__ float g_k1 [2080 * 64];
__device__ float g_vt1[2080 * 64];
__device__ float g_v1 [2080 * 64];
__device__ float g_k2 [8224 * 64];
__device__ float g_vt2[8224 * 64];
__device__ float g_v2 [8224 * 64];

// ---------------------------------------------------------------------------
// Weight repack (both SR convs): sr_w[o][c][p] -> wr[o][p*128 + c]
// ---------------------------------------------------------------------------
__global__ void repack_all(const float* __restrict__ s1, const float* __restrict__ s2) {
    int idx = blockIdx.x * 256 + threadIdx.x;
    constexpr int T1 = 128 * 16 * 128;
    constexpr int T2 = 128 * 4  * 128;
    if (idx < T1) {
        int o = idx / (16 * 128);
        int rem = idx % (16 * 128);
        int p = rem / 128, c = rem % 128;
        g_w1r[idx] = s1[(o * 128 + c) * 16 + p];
    } else if (idx < T1 + T2) {
        int j = idx - T1;
        int o = j / (4 * 128);
        int rem = j % (4 * 128);
        int p = rem / 128, c = rem % 128;
        g_w2r[j] = s2[(o * 128 + c) * 4 + p];
    }
}

// ---------------------------------------------------------------------------
// tf32 tensor-core tiled GEMM: C[M,128] = A[M,K] @ W[128,K]^T
//  MODE 0: Q proj -> g_q (+bias)        MODE 1: SR split-K partials -> g_p
//  MODE 2: KV proj -> g_k/g_vt (+bias)  MODE 3: out proj -> d_out (+bias+res)
// ---------------------------------------------------------------------------
template <int MODE, int BR>
__device__ __forceinline__ void gemm_dev(
    float* sA, float* sW,
    const float* __restrict__ x, const float* __restrict__ msg,
    const float* __restrict__ Wext, const float* __restrict__ bias,
    float* __restrict__ outext,
    int M, int Ktot, int tileM, int kb, int Ks, int splitIdx)
{
    const int tid = threadIdx.x;
    const float* Wp = (MODE == 1) ? (BR ? g_w2r : g_w1r) : Wext;

    const int lane = tid & 7;
    const int rq   = tid >> 3;

    const float* abase[4];
    bool avalid[4], aspat[4];
#pragma unroll
    for (int ps = 0; ps < 4; ++ps) {
        int grow = tileM + ps * 32 + rq;
        bool val = grow < M;
        avalid[ps] = val;
        aspat[ps]  = true;
        int g2 = val ? grow : 0;
        if (MODE == 0) {
            int b = g2 / NTOT, n = g2 % NTOT;
            abase[ps] = (n < N0)
                ? x   + (size_t)(b * N0   + n)        * 128 + lane * 4
                : msg + (size_t)(b * MSGN + (n - N0)) * 128 + lane * 4;
        } else if (MODE == 2) {
            const float* A = BR ? g_xk2 : g_xk1;
            abase[ps] = A + (size_t)g2 * 128 + lane * 4;
        } else if (MODE == 3) {
            abase[ps] = g_cat + (size_t)g2 * 128 + lane * 4;
        } else {
            constexpr int LMc = BrCfg<BR>::LM, Lc = BrCfg<BR>::L;
            constexpr int WRc = BrCfg<BR>::WR, Sc = BrCfg<BR>::S;
            int b = g2 / LMc, l = g2 % LMc;
            if (l < Lc) {
                int hr = l / WRc, wr = l % WRc;
                abase[ps] = x + (size_t)(b * N0 + (hr * Sc) * Wimg + wr * Sc) * 128 + lane * 4;
            } else {
                abase[ps] = msg + (size_t)(b * MSGN + (l - Lc)) * 128 + lane * 4;
                aspat[ps] = false;
            }
        }
    }

    const int warp   = tid >> 5;
    const int lane31 = tid & 31;
    const int warp_m = warp >> 1;
    const int warp_n = warp & 1;
    const int gid    = lane31 >> 2;
    const int tig    = lane31 & 3;

    float acc[2][8][4];
#pragma unroll
    for (int mt = 0; mt < 2; ++mt)
#pragma unroll
        for (int nt = 0; nt < 8; ++nt)
#pragma unroll
            for (int q = 0; q < 4; ++q) acc[mt][nt][q] = 0.f;

    for (int k0 = kb; k0 < kb + Ks; k0 += 32) {
#pragma unroll
        for (int ps = 0; ps < 4; ++ps) {
            int n = ps * 32 + rq;
            float4 w = *(const float4*)(Wp + (size_t)n * Ktot + k0 + lane * 4);
            sW[(lane * 4 + 0) * AST + n] = to_tf32(w.x);
            sW[(lane * 4 + 1) * AST + n] = to_tf32(w.y);
            sW[(lane * 4 + 2) * AST + n] = to_tf32(w.z);
            sW[(lane * 4 + 3) * AST + n] = to_tf32(w.w);
        }
        int aofs_s = k0, aofs_m = k0;
        if (MODE == 1) {
            constexpr int Sc = BrCfg<BR>::S;
            int p = k0 >> 7, c0 = k0 & 127;
            aofs_s = ((p / Sc) * Wimg + (p % Sc)) * 128 + c0;
            aofs_m = c0;
        }
#pragma unroll
        for (int ps = 0; ps < 4; ++ps) {
            int row = ps * 32 + rq;
            float4 a = make_float4(0.f, 0.f, 0.f, 0.f);
            if (avalid[ps])
                a = *(const float4*)(abase[ps] + (aspat[ps] ? aofs_s : aofs_m));
            sA[(lane * 4 + 0) * AST + row] = to_tf32(a.x);
            sA[(lane * 4 + 1) * AST + row] = to_tf32(a.y);
            sA[(lane * 4 + 2) * AST + row] = to_tf32(a.z);
            sA[(lane * 4 + 3) * AST + row] = to_tf32(a.w);
        }
        __syncthreads();

#pragma unroll
        for (int ks = 0; ks < 4; ++ks) {
            const int kr0 = ks * 8 + tig;
            unsigned afr[2][4];
#pragma unroll
            for (int mt = 0; mt < 2; ++mt) {
                int m = warp_m * 32 + mt * 16 + gid;
                afr[mt][0] = __float_as_uint(sA[kr0 * AST + m]);
                afr[mt][1] = __float_as_uint(sA[kr0 * AST + m + 8]);
                afr[mt][2] = __float_as_uint(sA[(kr0 + 4) * AST + m]);
                afr[mt][3] = __float_as_uint(sA[(kr0 + 4) * AST + m + 8]);
            }
#pragma unroll
            for (int nt = 0; nt < 8; ++nt) {
                int n = warp_n * 64 + nt * 8 + gid;
                unsigned b0 = __float_as_uint(sW[kr0 * AST + n]);
                unsigned b1 = __float_as_uint(sW[(kr0 + 4) * AST + n]);
                mma_tf32(acc[0][nt], afr[0], b0, b1);
                mma_tf32(acc[1][nt], afr[1], b0, b1);
            }
        }
        __syncthreads();
    }

    float bs[8][2];
    if (MODE != 1) {
#pragma unroll
        for (int nt = 0; nt < 8; ++nt) {
            int cn = warp_n * 64 + nt * 8 + 2 * tig;
            bs[nt][0] = bias[cn];
            bs[nt][1] = bias[cn + 1];
        }
    }

#pragma unroll
    for (int mt = 0; mt < 2; ++mt)
#pragma unroll
    for (int half = 0; half < 2; ++half) {
        int r = tileM + warp_m * 32 + mt * 16 + half * 8 + gid;
        if (r >= M) continue;
        if (MODE == 0) {
            float* o = g_q + (size_t)r * 128;
#pragma unroll
            for (int nt = 0; nt < 8; ++nt) {
                int cn = warp_n * 64 + nt * 8 + 2 * tig;
                *(float2*)(o + cn) = make_float2(acc[mt][nt][half * 2]     + bs[nt][0],
                                                 acc[mt][nt][half * 2 + 1] + bs[nt][1]);
            }
        } else if (MODE == 1) {
            float* o = (BR ? g_p2 : g_p1) + ((size_t)splitIdx * M + r) * 128;
#pragma unroll
            for (int nt = 0; nt < 8; ++nt) {
                int cn = warp_n * 64 + nt * 8 + 2 * tig;
                *(float2*)(o + cn) = make_float2(acc[mt][nt][half * 2],
                                                 acc[mt][nt][half * 2 + 1]);
            }
        } else if (MODE == 2) {
            float* ok = (BR ? g_k2  : g_k1 ) + (size_t)r * 64;
            float* ov = (BR ? g_vt2 : g_vt1) + (size_t)r * 64;
#pragma unroll
            for (int nt = 0; nt < 8; ++nt) {
                int cn = warp_n * 64 + nt * 8 + 2 * tig;
                float2 v = make_float2(acc[mt][nt][half * 2]     + bs[nt][0],
                                       acc[mt][nt][half * 2 + 1] + bs[nt][1]);
                if (cn < 64) *(float2*)(ok + cn)      = v;
                else         *(float2*)(ov + cn - 64) = v;
            }
        } else {
            int b = r / NTOT, n = r % NTOT;
            const float* res;
            float* o;
            if (n < N0) {
                res = x      + (size_t)(b * N0 + n) * 128;
                o   = outext + (size_t)(b * N0 + n) * 128;
            } else {
                res = msg    + (size_t)(b * MSGN + (n - N0)) * 128;
                o   = outext + OUT2_OFS + (size_t)(b * MSGN + (n - N0)) * 128;
            }
#pragma unroll
            for (int nt = 0; nt < 8; ++nt) {
                int cn = warp_n * 64 + nt * 8 + 2 * tig;
                float2 rv = *(const float2*)(res + cn);
                *(float2*)(o + cn) = make_float2(acc[mt][nt][half * 2]     + bs[nt][0] + rv.x,
                                                 acc[mt][nt][half * 2 + 1] + bs[nt][1] + rv.y);
            }
        }
    }
}

// ---------------------------------------------------------------------------
// Phase-1 fused: SR1 split-K (136) + SR2 split-K (130) + Qproj (257)
// ---------------------------------------------------------------------------
__global__ void __launch_bounds__(256, 2) phase1_k(
    const float* __restrict__ x, const float* __restrict__ msg,
    const float* __restrict__ Wq, const float* __restrict__ bq)
{
    __shared__ __align__(16) float sA[32 * AST];
    __shared__ __align__(16) float sW[32 * AST];
    int bx = blockIdx.x;
    if (bx < 136) {
        gemm_dev<1, 0>(sA, sW, x, msg, nullptr, nullptr, nullptr,
                       2080, 2048, (bx % 17) * 128, (bx / 17) * 256, 256, bx / 17);
    } else if (bx < 266) {
        int t = bx - 136;
        gemm_dev<1, 1>(sA, sW, x, msg, nullptr, nullptr, nullptr,
                       8224, 512, (t % 65) * 128, (t / 65) * 256, 256, t / 65);
    } else {
        int t = bx - 266;
        gemm_dev<0, 0>(sA, sW, x, msg, Wq, bq, nullptr,
                       MTOT, 128, t * 128, 0, 128, 0);
    }
}

__global__ void __launch_bounds__(256, 2) kv_k(
    const float* __restrict__ x, const float* __restrict__ msg,
    const float* __restrict__ kv1w, const float* __restrict__ kv1b,
    const float* __restrict__ kv2w, const float* __restrict__ kv2b)
{
    __shared__ __align__(16) float sA[32 * AST];
    __shared__ __align__(16) float sW[32 * AST];
    int bx = blockIdx.x;
    if (bx < 17)
        gemm_dev<2, 0>(sA, sW, x, msg, kv1w, kv1b, nullptr, 2080, 128, bx * 128, 0, 128, 0);
    else
        gemm_dev<2, 1>(sA, sW, x, msg, kv2w, kv2b, nullptr, 8224, 128, (bx - 17) * 128, 0, 128, 0);
}

__global__ void __launch_bounds__(256, 2) out_k(
    const float* __restrict__ x, const float* __restrict__ msg,
    const float* __restrict__ pw, const float* __restrict__ pb,
    float* __restrict__ out)
{
    __shared__ __align__(16) float sA[32 * AST];
    __shared__ __align__(16) float sW[32 * AST];
    gemm_dev<3, 0>(sA, sW, x, msg, pw, pb, out, MTOT, 128, blockIdx.x * 128, 0, 128, 0);
}

// ---------------------------------------------------------------------------
// Split-K reduce + bias + LayerNorm + exact GELU -> g_xk (both branches fused)
// ---------------------------------------------------------------------------
template <int BR>
__device__ __forceinline__ void sr_finish_dev(
    const float* __restrict__ bias, const float* __restrict__ lng,
    const float* __restrict__ lnb, int blk)
{
    constexpr int M  = BrCfg<BR>::M;
    constexpr int NS = BrCfg<BR>::NSPLIT;
    const float* part = BR ? g_p2 : g_p1;
    float* out        = BR ? g_xk2 : g_xk1;

    int warp  = threadIdx.x >> 5;
    int lanei = threadIdx.x & 31;
    int r = blk * 8 + warp;
    if (r >= M) return;

    float v[4];
    {
        float4 a = *(const float4*)(part + (size_t)r * 128 + lanei * 4);
        v[0] = a.x; v[1] = a.y; v[2] = a.z; v[3] = a.w;
    }
#pragma unroll
    for (int s = 1; s < NS; ++s) {
        float4 a = *(const float4*)(part + ((size_t)s * M + r) * 128 + lanei * 4);
        v[0] += a.x; v[1] += a.y; v[2] += a.z; v[3] += a.w;
    }
    {
        float4 bv = *(const float4*)(bias + lanei * 4);
        v[0] += bv.x; v[1] += bv.y; v[2] += bv.z; v[3] += bv.w;
    }
    float sum = v[0] + v[1] + v[2] + v[3];
    float sq  = v[0]*v[0] + v[1]*v[1] + v[2]*v[2] + v[3]*v[3];
#pragma unroll
    for (int ofs = 16; ofs >= 1; ofs >>= 1) {
        sum += __shfl_xor_sync(0xffffffffu, sum, ofs);
        sq  += __shfl_xor_sync(0xffffffffu, sq,  ofs);
    }
    float mean = sum * (1.f / 128.f);
    float var  = sq  * (1.f / 128.f) - mean * mean;
    float rstd = rsqrtf(var + 1e-5f);

    float4 gg = *(const float4*)(lng + lanei * 4);
    float4 bb = *(const float4*)(lnb + lanei * 4);
    float gv[4]  = {gg.x, gg.y, gg.z, gg.w};
    float bv2[4] = {bb.x, bb.y, bb.z, bb.w};
    float ov[4];
#pragma unroll
    for (int q2 = 0; q2 < 4; ++q2) {
        float t = (v[q2] - mean) * rstd * gv[q2] + bv2[q2];
        ov[q2] = 0.5f * t * (1.f + erff(t * 0.70710678118654752f));
    }
    *(float4*)(out + (size_t)r * 128 + lanei * 4) = make_float4(ov[0], ov[1], ov[2], ov[3]);
}

__global__ void finish_all(
    const float* __restrict__ b1, const float* __restrict__ g1, const float* __restrict__ lb1,
    const float* __restrict__ b2, const float* __restrict__ g2, const float* __restrict__ lb2)
{
    if (blockIdx.x < 260) sr_finish_dev<0>(b1, g1, lb1, blockIdx.x);
    else                  sr_finish_dev<1>(b2, g2, lb2, blockIdx.x - 260);
}

// ---------------------------------------------------------------------------
// V fix-up: spatial rows -> v + dwconv3x3(v) + lc_b ; msg rows -> 2*v (fused)
// ---------------------------------------------------------------------------
template <int BR>
__device__ __forceinline__ void lc_dev(const float* __restrict__ lw,
                                       const float* __restrict__ lb, int idx)
{
    constexpr int LM = BrCfg<BR>::LM, L = BrCfg<BR>::L, WR = BrCfg<BR>::WR;
    const float* vt = BR ? g_vt2 : g_vt1;
    float* vo       = BR ? g_v2  : g_v1;
    if (idx >= Bb * LM * 64) return;
    int ch   = idx & 63;
    int rest = idx >> 6;
    int l = rest % LM, b = rest / LM;
    float c = vt[idx];
    if (l >= L) { vo[idx] = 2.f * c; return; }
    int hr = l / WR, wr = l % WR;
    float a = lb[ch];
#pragma unroll
    for (int di = 0; di < 3; ++di)
#pragma unroll
        for (int dj = 0; dj < 3; ++dj) {
            int nh = hr + di - 1, nw = wr + dj - 1;
            if (nh >= 0 && nh < WR && nw >= 0 && nw < WR)
                a += vt[((size_t)(b * LM) + nh * WR + nw) * 64 + ch] * lw[ch * 9 + di * 3 + dj];
        }
    vo[idx] = c + a;
}

__global__ void lc_all(const float* __restrict__ w1, const float* __restrict__ b1,
                       const float* __restrict__ w2, const float* __restrict__ b2)
{
    int bx = blockIdx.x;
    if (bx < 520) lc_dev<0>(w1, b1, bx * 256 + threadIdx.x);
    else          lc_dev<1>(w2, b2, (bx - 520) * 256 + threadIdx.x);
}

// ---------------------------------------------------------------------------
// Tensor-core flash attention (tf32 mma, fp32 softmax state).
// 256 thr = 8 warps; warp owns 16 query rows; keys streamed in 32-row chunks.
// S = Q@K^T via m16n8k8; P staged through per-warp smem (layout conversion);
// O += P@V via m16n8k8. Online softmax with register-level masking.
// ---------------------------------------------------------------------------
template <int BR>
__device__ __forceinline__ void attn_dev(float* Ks, float* Vs, float* Ps)
{
    constexpr int LM   = BrCfg<BR>::LM;
    constexpr int QOFS = BR ? 64 : 0;
    constexpr float SCALE = 0.17677669529663687f;  // 32^-0.5
    const float* gk = BR ? g_k2 : g_k1;
    const float* gv = BR ? g_v2 : g_v1;

    const int b      = blockIdx.y >> 1;
    const int h      = blockIdx.y & 1;
    const int tid    = threadIdx.x;
    const int w      = tid >> 5;
    const int lane31 = tid & 31;
    const int gid    = lane31 >> 2;   // 0..7
    const int tig    = lane31 & 3;    // 0..3

    const int qbase = blockIdx.x * 128 + w * 16;
    const int r0 = qbase + gid, r1 = qbase + gid + 8;
    const bool v0 = r0 < NTOT, v1 = r1 < NTOT;
    const int rc0 = v0 ? r0 : NTOT - 1, rc1 = v1 ? r1 : NTOT - 1;

    // Q fragments (load once, tf32-rounded)
    const float* q0p = g_q + (size_t)(b * NTOT + rc0) * 128 + QOFS + h * 32;
    const float* q1p = g_q + (size_t)(b * NTOT + rc1) * 128 + QOFS + h * 32;
    unsigned aq[4][4];
#pragma unroll
    for (int ks = 0; ks < 4; ++ks) {
        aq[ks][0] = __float_as_uint(to_tf32(q0p[8 * ks + tig]));
        aq[ks][1] = __float_as_uint(to_tf32(q1p[8 * ks + tig]));
        aq[ks][2] = __float_as_uint(to_tf32(q0p[8 * ks + tig + 4]));
        aq[ks][3] = __float_as_uint(to_tf32(q1p[8 * ks + tig + 4]));
    }

    float o[4][4];
#pragma unroll
    for (int nt = 0; nt < 4; ++nt)
#pragma unroll
        for (int q = 0; q < 4; ++q) o[nt][q] = 0.f;
    float m0 = -1e30f, m1 = -1e30f, l0 = 0.f, l1 = 0.f;

    float* Pw = Ps + w * (16 * 34);
    const int ldr = tid >> 3;          // 0..31 (K/V cooperative load row)
    const int ldc = (tid & 7) * 4;

    for (int c0 = 0; c0 < LM; c0 += 32) {
        __syncthreads();
        // K/V chunk -> smem (tf32-rounded; OOB rows zeroed, masked later)
        {
            int src = c0 + ldr;
            float4 kk = make_float4(0.f, 0.f, 0.f, 0.f);
            float4 vv = make_float4(0.f, 0.f, 0.f, 0.f);
            if (src < LM) {
                size_t base = (size_t)(b * LM + src) * 64 + h * 32 + ldc;
                kk = *(const float4*)(gk + base);
                vv = *(const float4*)(gv + base);
            }
            float* kd = Ks + ldr * 33 + ldc;
            kd[0] = to_tf32(kk.x); kd[1] = to_tf32(kk.y);
            kd[2] = to_tf32(kk.z); kd[3] = to_tf32(kk.w);
            float* vd = Vs + ldr * 33 + ldc;
            vd[0] = to_tf32(vv.x); vd[1] = to_tf32(vv.y);
            vd[2] = to_tf32(vv.z); vd[3] = to_tf32(vv.w);
        }
        __syncthreads();

        // ---- S = Q @ K^T (16 mma) ----
        float s[4][4];
#pragma unroll
        for (int nt = 0; nt < 4; ++nt) {
            s[nt][0] = s[nt][1] = s[nt][2] = s[nt][3] = 0.f;
            const float* kr = Ks + (nt * 8 + gid) * 33;
#pragma unroll
            for (int ks = 0; ks < 4; ++ks) {
                unsigned b0 = __float_as_uint(kr[8 * ks + tig]);
                unsigned b1 = __float_as_uint(kr[8 * ks + tig + 4]);
                mma_tf32(s[nt], aq[ks], b0, b1);
            }
        }

        // ---- scale + mask + row max ----
        float m0loc = -1e30f, m1loc = -1e30f;
#pragma unroll
        for (int nt = 0; nt < 4; ++nt) {
            int key = c0 + nt * 8 + 2 * tig;
            bool k0v = key < LM, k1v = (key + 1) < LM;
            s[nt][0] = k0v ? s[nt][0] * SCALE : -1e30f;
            s[nt][1] = k1v ? s[nt][1] * SCALE : -1e30f;
            s[nt][2] = k0v ? s[nt][2] * SCALE : -1e30f;
            s[nt][3] = k1v ? s[nt][3] * SCALE : -1e30f;
            m0loc = fmaxf(m0loc, fmaxf(s[nt][0], s[nt][1]));
            m1loc = fmaxf(m1loc, fmaxf(s[nt][2], s[nt][3]));
        }
        m0loc = fmaxf(m0loc, __shfl_xor_sync(0xffffffffu, m0loc, 1));
        m0loc = fmaxf(m0loc, __shfl_xor_sync(0xffffffffu, m0loc, 2));
        m1loc = fmaxf(m1loc, __shfl_xor_sync(0xffffffffu, m1loc, 1));
        m1loc = fmaxf(m1loc, __shfl_xor_sync(0xffffffffu, m1loc, 2));
        float mn0 = fmaxf(m0, m0loc), mn1 = fmaxf(m1, m1loc);
        float cr0 = __expf(m0 - mn0), cr1 = __expf(m1 - mn1);

        // ---- P = exp(s - m), staged to per-warp smem (tf32) ----
        float ls0 = 0.f, ls1 = 0.f;
#pragma unroll
        for (int nt = 0; nt < 4; ++nt) {
            float p00 = to_tf32(__expf(s[nt][0] - mn0));
            float p01 = to_tf32(__expf(s[nt][1] - mn0));
            float p10 = to_tf32(__expf(s[nt][2] - mn1));
            float p11 = to_tf32(__expf(s[nt][3] - mn1));
            ls0 += p00 + p01;
            ls1 += p10 + p11;
            *(float2*)(Pw + gid * 34 + nt * 8 + 2 * tig)       = make_float2(p00, p01);
            *(float2*)(Pw + (gid + 8) * 34 + nt * 8 + 2 * tig) = make_float2(p10, p11);
        }
        ls0 += __shfl_xor_sync(0xffffffffu, ls0, 1);
        ls0 += __shfl_xor_sync(0xffffffffu, ls0, 2);
        ls1 += __shfl_xor_sync(0xffffffffu, ls1, 1);
        ls1 += __shfl_xor_sync(0xffffffffu, ls1, 2);
        l0 = l0 * cr0 + ls0;
        l1 = l1 * cr1 + ls1;
#pragma unroll
        for (int nt = 0; nt < 4; ++nt) {
            o[nt][0] *= cr0; o[nt][1] *= cr0;
            o[nt][2] *= cr1; o[nt][3] *= cr1;
        }
        m0 = mn0; m1 = mn1;
        __syncwarp();

        // ---- O += P @ V (16 mma) ----
#pragma unroll
        for (int ks = 0; ks < 4; ++ks) {
            unsigned ap[4];
            ap[0] = __float_as_uint(Pw[gid * 34 + 8 * ks + tig]);
            ap[1] = __float_as_uint(Pw[(gid + 8) * 34 + 8 * ks + tig]);
            ap[2] = __float_as_uint(Pw[gid * 34 + 8 * ks + tig + 4]);
            ap[3] = __float_as_uint(Pw[(gid + 8) * 34 + 8 * ks + tig + 4]);
            const float* vr0 = Vs + (8 * ks + tig) * 33;
            const float* vr1 = Vs + (8 * ks + tig + 4) * 33;
#pragma unroll
            for (int nt = 0; nt < 4; ++nt) {
                unsigned b0 = __float_as_uint(vr0[nt * 8 + gid]);
                unsigned b1 = __float_as_uint(vr1[nt * 8 + gid]);
                mma_tf32(o[nt], ap, b0, b1);
            }
        }
    }

    // ---- normalize + store ----
    float i0 = 1.f / l0, i1 = 1.f / l1;
    if (v0) {
        float* op = g_cat + (size_t)(b * NTOT + r0) * 128 + QOFS + h * 32;
#pragma unroll
        for (int nt = 0; nt < 4; ++nt)
            *(float2*)(op + nt * 8 + 2 * tig) = make_float2(o[nt][0] * i0, o[nt][1] * i0);
    }
    if (v1) {
        float* op = g_cat + (size_t)(b * NTOT + r1) * 128 + QOFS + h * 32;
#pragma unroll
        for (int nt = 0; nt < 4; ++nt)
            *(float2*)(op + nt * 8 + 2 * tig) = make_float2(o[nt][2] * i1, o[nt][3] * i1);
    }
}

__global__ void __launch_bounds__(256) attn_all()
{
    __shared__ __align__(16) float Ks[32 * 33];
    __shared__ __align__(16) float Vs[32 * 33];
    __shared__ __align__(16) float Ps[8 * 16 * 34];
    if (blockIdx.z == 0) attn_dev<0>(Ks, Vs, Ps);
    else                 attn_dev<1>(Ks, Vs, Ps);
}

// ---------------------------------------------------------------------------
// Launch
// ---------------------------------------------------------------------------
extern "C" void kernel_launch(void* const* d_in, const int* in_sizes, int n_in,
                              void* d_out, int out_size)
{
    (void)in_sizes; (void)n_in; (void)out_size;
    const float* x     = (const float*)d_in[0];
    const float* msg   = (const float*)d_in[1];
    const float* Wq    = (const float*)d_in[2];
    const float* bq    = (const float*)d_in[3];
    const float* sr1w  = (const float*)d_in[4];
    const float* sr1b  = (const float*)d_in[5];
    const float* ln1g  = (const float*)d_in[6];
    const float* ln1b  = (const float*)d_in[7];
    const float* sr2w  = (const float*)d_in[8];
    const float* sr2b  = (const float*)d_in[9];
    const float* ln2g  = (const float*)d_in[10];
    const float* ln2b  = (const float*)d_in[11];
    const float* kv1w  = (const float*)d_in[12];
    const float* kv1b  = (const float*)d_in[13];
    const float* kv2w  = (const float*)d_in[14];
    const float* kv2b  = (const float*)d_in[15];
    const float* lc1w  = (const float*)d_in[16];
    const float* lc1b  = (const float*)d_in[17];
    const float* lc2w  = (const float*)d_in[18];
    const float* lc2b  = (const float*)d_in[19];
    const float* projw = (const float*)d_in[20];
    const float* projb = (const float*)d_in[21];
    float* out = (float*)d_out;

    // SR conv weight repack (both)
    repack_all<<<1280, 256>>>(sr1w, sr2w);

    // Fused: SR1 split-K + SR2 split-K + Q projection (tf32 mma)
    phase1_k<<<523, 256>>>(x, msg, Wq, bq);

    // Fused reduce + bias + LN + GELU
    finish_all<<<1288, 256>>>(sr1b, ln1g, ln1b, sr2b, ln2g, ln2b);

    // Fused KV projections (tf32 mma)
    kv_k<<<82, 256>>>(x, msg, kv1w, kv1b, kv2w, kv2b);

    // Fused depthwise 3x3 V fix-up
    lc_all<<<2576, 256>>>(lc1w, lc1b, lc2w, lc2b);

    // Tensor-core flash attention (both branches)
    attn_all<<<dim3(33, 16, 2), 256>>>();

    // Output projection + residual + split store (tf32 mma)
    out_k<<<257, 256>>>(x, msg, projw, projb, out);
}

// round 8
// speedup vs baseline: 2.7256x; 1.4064x over previous
#include <cuda_runtime.h>
#include <math.h>

typedef unsigned long long ull;

// ---------------------------------------------------------------------------
// tf32 helpers
// ---------------------------------------------------------------------------
__device__ __forceinline__ float to_tf32(float f) {
    unsigned r;
    asm("cvt.rna.tf32.f32 %0, %1;" : "=r"(r) : "f"(f));
    return __uint_as_float(r);
}
__device__ __forceinline__ void mma_tf32(float* c, const unsigned* a, unsigned b0, unsigned b1) {
    asm volatile(
        "mma.sync.aligned.m16n8k8.row.col.f32.tf32.tf32.f32 "
        "{%0,%1,%2,%3},{%4,%5,%6,%7},{%8,%9},{%0,%1,%2,%3};"
        : "+f"(c[0]), "+f"(c[1]), "+f"(c[2]), "+f"(c[3])
        : "r"(a[0]), "r"(a[1]), "r"(a[2]), "r"(a[3]), "r"(b0), "r"(b1));
}

// cp.async 16B (zero-fill when sz==0)
__device__ __forceinline__ void cp_async16(unsigned saddr, const void* gptr, int sz) {
    asm volatile("cp.async.cg.shared.global [%0], [%1], 16, %2;"
                 :: "r"(saddr), "l"(gptr), "r"(sz));
}
__device__ __forceinline__ void cp_commit() { asm volatile("cp.async.commit_group;"); }
__device__ __forceinline__ void cp_wait1()  { asm volatile("cp.async.wait_group 1;"); }

// ---------------------------------------------------------------------------
// Problem constants
// ---------------------------------------------------------------------------
constexpr int Bb   = 8;
constexpr int Cc   = 128;
constexpr int N0   = 4096;
constexpr int MSGN = 4;
constexpr int NTOT = N0 + MSGN;  // 4100
constexpr int Wimg = 64;
constexpr int MTOT = Bb * NTOT;  // 32800
constexpr size_t OUT2_OFS = (size_t)Bb * N0 * Cc;
constexpr int AST = 132;
constexpr int KVST = 36;         // K/V smem row stride (16B-aligned for cp.async)

template <int BR> struct BrCfg;
template <> struct BrCfg<0> {
    static constexpr int S = 4, WR = 16, L = 256, LM = 260, K = 2048, NSPLIT = 8, M = Bb * 260;
};
template <> struct BrCfg<1> {
    static constexpr int S = 2, WR = 32, L = 1024, LM = 1028, K = 512, NSPLIT = 2, M = Bb * 1028;
};

// ---------------------------------------------------------------------------
// Scratch (device globals — no allocation allowed)
// ---------------------------------------------------------------------------
__device__ float g_q  [MTOT * Cc];
__device__ float g_cat[MTOT * Cc];
__device__ float g_w1r[128 * 2048];
__device__ float g_w2r[128 * 512];
__device__ float g_p1 [8 * 2080 * 128];
__device__ float g_p2 [2 * 8224 * 128];
__device__ float g_xk1[2080 * 128];
__device__ float g_xk2[8224 * 128];
__device__ float g_k1 [2080 * 64];
__device__ float g_vt1[2080 * 64];
__device__ float g_v1 [2080 * 64];
__device__ float g_k2 [8224 * 64];
__device__ float g_vt2[8224 * 64];
__device__ float g_v2 [8224 * 64];

// ---------------------------------------------------------------------------
// Weight repack (both SR convs): sr_w[o][c][p] -> wr[o][p*128 + c]
// ---------------------------------------------------------------------------
__global__ void repack_all(const float* __restrict__ s1, const float* __restrict__ s2) {
    int idx = blockIdx.x * 256 + threadIdx.x;
    constexpr int T1 = 128 * 16 * 128;
    constexpr int T2 = 128 * 4  * 128;
    if (idx < T1) {
        int o = idx / (16 * 128);
        int rem = idx % (16 * 128);
        int p = rem / 128, c = rem % 128;
        g_w1r[idx] = s1[(o * 128 + c) * 16 + p];
    } else if (idx < T1 + T2) {
        int j = idx - T1;
        int o = j / (4 * 128);
        int rem = j % (4 * 128);
        int p = rem / 128, c = rem % 128;
        g_w2r[j] = s2[(o * 128 + c) * 4 + p];
    }
}

// ---------------------------------------------------------------------------
// tf32 tensor-core tiled GEMM: C[M,128] = A[M,K] @ W[128,K]^T
// ---------------------------------------------------------------------------
template <int MODE, int BR>
__device__ __forceinline__ void gemm_dev(
    float* sA, float* sW,
    const float* __restrict__ x, const float* __restrict__ msg,
    const float* __restrict__ Wext, const float* __restrict__ bias,
    float* __restrict__ outext,
    int M, int Ktot, int tileM, int kb, int Ks, int splitIdx)
{
    const int tid = threadIdx.x;
    const float* Wp = (MODE == 1) ? (BR ? g_w2r : g_w1r) : Wext;

    const int lane = tid & 7;
    const int rq   = tid >> 3;

    const float* abase[4];
    bool avalid[4], aspat[4];
#pragma unroll
    for (int ps = 0; ps < 4; ++ps) {
        int grow = tileM + ps * 32 + rq;
        bool val = grow < M;
        avalid[ps] = val;
        aspat[ps]  = true;
        int g2 = val ? grow : 0;
        if (MODE == 0) {
            int b = g2 / NTOT, n = g2 % NTOT;
            abase[ps] = (n < N0)
                ? x   + (size_t)(b * N0   + n)        * 128 + lane * 4
                : msg + (size_t)(b * MSGN + (n - N0)) * 128 + lane * 4;
        } else if (MODE == 2) {
            const float* A = BR ? g_xk2 : g_xk1;
            abase[ps] = A + (size_t)g2 * 128 + lane * 4;
        } else if (MODE == 3) {
            abase[ps] = g_cat + (size_t)g2 * 128 + lane * 4;
        } else {
            constexpr int LMc = BrCfg<BR>::LM, Lc = BrCfg<BR>::L;
            constexpr int WRc = BrCfg<BR>::WR, Sc = BrCfg<BR>::S;
            int b = g2 / LMc, l = g2 % LMc;
            if (l < Lc) {
                int hr = l / WRc, wr = l % WRc;
                abase[ps] = x + (size_t)(b * N0 + (hr * Sc) * Wimg + wr * Sc) * 128 + lane * 4;
            } else {
                abase[ps] = msg + (size_t)(b * MSGN + (l - Lc)) * 128 + lane * 4;
                aspat[ps] = false;
            }
        }
    }

    const int warp   = tid >> 5;
    const int lane31 = tid & 31;
    const int warp_m = warp >> 1;
    const int warp_n = warp & 1;
    const int gid    = lane31 >> 2;
    const int tig    = lane31 & 3;

    float acc[2][8][4];
#pragma unroll
    for (int mt = 0; mt < 2; ++mt)
#pragma unroll
        for (int nt = 0; nt < 8; ++nt)
#pragma unroll
            for (int q = 0; q < 4; ++q) acc[mt][nt][q] = 0.f;

    for (int k0 = kb; k0 < kb + Ks; k0 += 32) {
#pragma unroll
        for (int ps = 0; ps < 4; ++ps) {
            int n = ps * 32 + rq;
            float4 w = *(const float4*)(Wp + (size_t)n * Ktot + k0 + lane * 4);
            sW[(lane * 4 + 0) * AST + n] = to_tf32(w.x);
            sW[(lane * 4 + 1) * AST + n] = to_tf32(w.y);
            sW[(lane * 4 + 2) * AST + n] = to_tf32(w.z);
            sW[(lane * 4 + 3) * AST + n] = to_tf32(w.w);
        }
        int aofs_s = k0, aofs_m = k0;
        if (MODE == 1) {
            constexpr int Sc = BrCfg<BR>::S;
            int p = k0 >> 7, c0 = k0 & 127;
            aofs_s = ((p / Sc) * Wimg + (p % Sc)) * 128 + c0;
            aofs_m = c0;
        }
#pragma unroll
        for (int ps = 0; ps < 4; ++ps) {
            int row = ps * 32 + rq;
            float4 a = make_float4(0.f, 0.f, 0.f, 0.f);
            if (avalid[ps])
                a = *(const float4*)(abase[ps] + (aspat[ps] ? aofs_s : aofs_m));
            sA[(lane * 4 + 0) * AST + row] = to_tf32(a.x);
            sA[(lane * 4 + 1) * AST + row] = to_tf32(a.y);
            sA[(lane * 4 + 2) * AST + row] = to_tf32(a.z);
            sA[(lane * 4 + 3) * AST + row] = to_tf32(a.w);
        }
        __syncthreads();

#pragma unroll
        for (int ks = 0; ks < 4; ++ks) {
            const int kr0 = ks * 8 + tig;
            unsigned afr[2][4];
#pragma unroll
            for (int mt = 0; mt < 2; ++mt) {
                int m = warp_m * 32 + mt * 16 + gid;
                afr[mt][0] = __float_as_uint(sA[kr0 * AST + m]);
                afr[mt][1] = __float_as_uint(sA[kr0 * AST + m + 8]);
                afr[mt][2] = __float_as_uint(sA[(kr0 + 4) * AST + m]);
                afr[mt][3] = __float_as_uint(sA[(kr0 + 4) * AST + m + 8]);
            }
#pragma unroll
            for (int nt = 0; nt < 8; ++nt) {
                int n = warp_n * 64 + nt * 8 + gid;
                unsigned b0 = __float_as_uint(sW[kr0 * AST + n]);
                unsigned b1 = __float_as_uint(sW[(kr0 + 4) * AST + n]);
                mma_tf32(acc[0][nt], afr[0], b0, b1);
                mma_tf32(acc[1][nt], afr[1], b0, b1);
            }
        }
        __syncthreads();
    }

    float bs[8][2];
    if (MODE != 1) {
#pragma unroll
        for (int nt = 0; nt < 8; ++nt) {
            int cn = warp_n * 64 + nt * 8 + 2 * tig;
            bs[nt][0] = bias[cn];
            bs[nt][1] = bias[cn + 1];
        }
    }

#pragma unroll
    for (int mt = 0; mt < 2; ++mt)
#pragma unroll
    for (int half = 0; half < 2; ++half) {
        int r = tileM + warp_m * 32 + mt * 16 + half * 8 + gid;
        if (r >= M) continue;
        if (MODE == 0) {
            float* o = g_q + (size_t)r * 128;
#pragma unroll
            for (int nt = 0; nt < 8; ++nt) {
                int cn = warp_n * 64 + nt * 8 + 2 * tig;
                *(float2*)(o + cn) = make_float2(acc[mt][nt][half * 2]     + bs[nt][0],
                                                 acc[mt][nt][half * 2 + 1] + bs[nt][1]);
            }
        } else if (MODE == 1) {
            float* o = (BR ? g_p2 : g_p1) + ((size_t)splitIdx * M + r) * 128;
#pragma unroll
            for (int nt = 0; nt < 8; ++nt) {
                int cn = warp_n * 64 + nt * 8 + 2 * tig;
                *(float2*)(o + cn) = make_float2(acc[mt][nt][half * 2],
                                                 acc[mt][nt][half * 2 + 1]);
            }
        } else if (MODE == 2) {
            float* ok = (BR ? g_k2  : g_k1 ) + (size_t)r * 64;
            float* ov = (BR ? g_vt2 : g_vt1) + (size_t)r * 64;
#pragma unroll
            for (int nt = 0; nt < 8; ++nt) {
                int cn = warp_n * 64 + nt * 8 + 2 * tig;
                float2 v = make_float2(acc[mt][nt][half * 2]     + bs[nt][0],
                                       acc[mt][nt][half * 2 + 1] + bs[nt][1]);
                if (cn < 64) *(float2*)(ok + cn)      = v;
                else         *(float2*)(ov + cn - 64) = v;
            }
        } else {
            int b = r / NTOT, n = r % NTOT;
            const float* res;
            float* o;
            if (n < N0) {
                res = x      + (size_t)(b * N0 + n) * 128;
                o   = outext + (size_t)(b * N0 + n) * 128;
            } else {
                res = msg    + (size_t)(b * MSGN + (n - N0)) * 128;
                o   = outext + OUT2_OFS + (size_t)(b * MSGN + (n - N0)) * 128;
            }
#pragma unroll
            for (int nt = 0; nt < 8; ++nt) {
                int cn = warp_n * 64 + nt * 8 + 2 * tig;
                float2 rv = *(const float2*)(res + cn);
                *(float2*)(o + cn) = make_float2(acc[mt][nt][half * 2]     + bs[nt][0] + rv.x,
                                                 acc[mt][nt][half * 2 + 1] + bs[nt][1] + rv.y);
            }
        }
    }
}

// ---------------------------------------------------------------------------
// Phase-1 fused: SR1 split-K (136) + SR2 split-K (130) + Qproj (257)
// ---------------------------------------------------------------------------
__global__ void __launch_bounds__(256, 2) phase1_k(
    const float* __restrict__ x, const float* __restrict__ msg,
    const float* __restrict__ Wq, const float* __restrict__ bq)
{
    __shared__ __align__(16) float sA[32 * AST];
    __shared__ __align__(16) float sW[32 * AST];
    int bx = blockIdx.x;
    if (bx < 136) {
        gemm_dev<1, 0>(sA, sW, x, msg, nullptr, nullptr, nullptr,
                       2080, 2048, (bx % 17) * 128, (bx / 17) * 256, 256, bx / 17);
    } else if (bx < 266) {
        int t = bx - 136;
        gemm_dev<1, 1>(sA, sW, x, msg, nullptr, nullptr, nullptr,
                       8224, 512, (t % 65) * 128, (t / 65) * 256, 256, t / 65);
    } else {
        int t = bx - 266;
        gemm_dev<0, 0>(sA, sW, x, msg, Wq, bq, nullptr,
                       MTOT, 128, t * 128, 0, 128, 0);
    }
}

__global__ void __launch_bounds__(256, 2) kv_k(
    const float* __restrict__ x, const float* __restrict__ msg,
    const float* __restrict__ kv1w, const float* __restrict__ kv1b,
    const float* __restrict__ kv2w, const float* __restrict__ kv2b)
{
    __shared__ __align__(16) float sA[32 * AST];
    __shared__ __align__(16) float sW[32 * AST];
    int bx = blockIdx.x;
    if (bx < 17)
        gemm_dev<2, 0>(sA, sW, x, msg, kv1w, kv1b, nullptr, 2080, 128, bx * 128, 0, 128, 0);
    else
        gemm_dev<2, 1>(sA, sW, x, msg, kv2w, kv2b, nullptr, 8224, 128, (bx - 17) * 128, 0, 128, 0);
}

__global__ void __launch_bounds__(256, 2) out_k(
    const float* __restrict__ x, const float* __restrict__ msg,
    const float* __restrict__ pw, const float* __restrict__ pb,
    float* __restrict__ out)
{
    __shared__ __align__(16) float sA[32 * AST];
    __shared__ __align__(16) float sW[32 * AST];
    gemm_dev<3, 0>(sA, sW, x, msg, pw, pb, out, MTOT, 128, blockIdx.x * 128, 0, 128, 0);
}

// ---------------------------------------------------------------------------
// Split-K reduce + bias + LayerNorm + exact GELU -> g_xk (both branches fused)
// ---------------------------------------------------------------------------
template <int BR>
__device__ __forceinline__ void sr_finish_dev(
    const float* __restrict__ bias, const float* __restrict__ lng,
    const float* __restrict__ lnb, int blk)
{
    constexpr int M  = BrCfg<BR>::M;
    constexpr int NS = BrCfg<BR>::NSPLIT;
    const float* part = BR ? g_p2 : g_p1;
    float* out        = BR ? g_xk2 : g_xk1;

    int warp  = threadIdx.x >> 5;
    int lanei = threadIdx.x & 31;
    int r = blk * 8 + warp;
    if (r >= M) return;

    float v[4];
    {
        float4 a = *(const float4*)(part + (size_t)r * 128 + lanei * 4);
        v[0] = a.x; v[1] = a.y; v[2] = a.z; v[3] = a.w;
    }
#pragma unroll
    for (int s = 1; s < NS; ++s) {
        float4 a = *(const float4*)(part + ((size_t)s * M + r) * 128 + lanei * 4);
        v[0] += a.x; v[1] += a.y; v[2] += a.z; v[3] += a.w;
    }
    {
        float4 bv = *(const float4*)(bias + lanei * 4);
        v[0] += bv.x; v[1] += bv.y; v[2] += bv.z; v[3] += bv.w;
    }
    float sum = v[0] + v[1] + v[2] + v[3];
    float sq  = v[0]*v[0] + v[1]*v[1] + v[2]*v[2] + v[3]*v[3];
#pragma unroll
    for (int ofs = 16; ofs >= 1; ofs >>= 1) {
        sum += __shfl_xor_sync(0xffffffffu, sum, ofs);
        sq  += __shfl_xor_sync(0xffffffffu, sq,  ofs);
    }
    float mean = sum * (1.f / 128.f);
    float var  = sq  * (1.f / 128.f) - mean * mean;
    float rstd = rsqrtf(var + 1e-5f);

    float4 gg = *(const float4*)(lng + lanei * 4);
    float4 bb = *(const float4*)(lnb + lanei * 4);
    float gv[4]  = {gg.x, gg.y, gg.z, gg.w};
    float bv2[4] = {bb.x, bb.y, bb.z, bb.w};
    float ov[4];
#pragma unroll
    for (int q2 = 0; q2 < 4; ++q2) {
        float t = (v[q2] - mean) * rstd * gv[q2] + bv2[q2];
        ov[q2] = 0.5f * t * (1.f + erff(t * 0.70710678118654752f));
    }
    *(float4*)(out + (size_t)r * 128 + lanei * 4) = make_float4(ov[0], ov[1], ov[2], ov[3]);
}

__global__ void finish_all(
    const float* __restrict__ b1, const float* __restrict__ g1, const float* __restrict__ lb1,
    const float* __restrict__ b2, const float* __restrict__ g2, const float* __restrict__ lb2)
{
    if (blockIdx.x < 260) sr_finish_dev<0>(b1, g1, lb1, blockIdx.x);
    else                  sr_finish_dev<1>(b2, g2, lb2, blockIdx.x - 260);
}

// ---------------------------------------------------------------------------
// V fix-up: spatial rows -> v + dwconv3x3(v) + lc_b ; msg rows -> 2*v (fused)
// ---------------------------------------------------------------------------
template <int BR>
__device__ __forceinline__ void lc_dev(const float* __restrict__ lw,
                                       const float* __restrict__ lb, int idx)
{
    constexpr int LM = BrCfg<BR>::LM, L = BrCfg<BR>::L, WR = BrCfg<BR>::WR;
    const float* vt = BR ? g_vt2 : g_vt1;
    float* vo       = BR ? g_v2  : g_v1;
    if (idx >= Bb * LM * 64) return;
    int ch   = idx & 63;
    int rest = idx >> 6;
    int l = rest % LM, b = rest / LM;
    float c = vt[idx];
    if (l >= L) { vo[idx] = 2.f * c; return; }
    int hr = l / WR, wr = l % WR;
    float a = lb[ch];
#pragma unroll
    for (int di = 0; di < 3; ++di)
#pragma unroll
        for (int dj = 0; dj < 3; ++dj) {
            int nh = hr + di - 1, nw = wr + dj - 1;
            if (nh >= 0 && nh < WR && nw >= 0 && nw < WR)
                a += vt[((size_t)(b * LM) + nh * WR + nw) * 64 + ch] * lw[ch * 9 + di * 3 + dj];
        }
    vo[idx] = c + a;
}

__global__ void lc_all(const float* __restrict__ w1, const float* __restrict__ b1,
                       const float* __restrict__ w2, const float* __restrict__ b2)
{
    int bx = blockIdx.x;
    if (bx < 520) lc_dev<0>(w1, b1, bx * 256 + threadIdx.x);
    else          lc_dev<1>(w2, b2, (bx - 520) * 256 + threadIdx.x);
}

// ---------------------------------------------------------------------------
// Tensor-core flash attention, double-buffered cp.async K/V prefetch.
// 256 thr = 8 warps; warp owns 16 query rows; keys streamed in 32-row chunks.
// tf32 mma with raw fp32 operands (implicit RZ truncation to tf32 by HW).
// ---------------------------------------------------------------------------
template <int BR>
__device__ __forceinline__ void attn_dev(float* Ks, float* Vs, float* Ps)
{
    constexpr int LM   = BrCfg<BR>::LM;
    constexpr int NCH  = (LM + 31) / 32;
    constexpr int QOFS = BR ? 64 : 0;
    constexpr float SCALE = 0.17677669529663687f;  // 32^-0.5
    const float* gk = BR ? g_k2 : g_k1;
    const float* gv = BR ? g_v2 : g_v1;

    const int b      = blockIdx.y >> 1;
    const int h      = blockIdx.y & 1;
    const int tid    = threadIdx.x;
    const int w      = tid >> 5;
    const int lane31 = tid & 31;
    const int gid    = lane31 >> 2;   // 0..7
    const int tig    = lane31 & 3;    // 0..3

    const int qbase = blockIdx.x * 128 + w * 16;
    const int r0 = qbase + gid, r1 = qbase + gid + 8;
    const bool v0 = r0 < NTOT, v1 = r1 < NTOT;
    const int rc0 = v0 ? r0 : NTOT - 1, rc1 = v1 ? r1 : NTOT - 1;

    // Q fragments (raw fp32 — HW truncates to tf32)
    const float* q0p = g_q + (size_t)(b * NTOT + rc0) * 128 + QOFS + h * 32;
    const float* q1p = g_q + (size_t)(b * NTOT + rc1) * 128 + QOFS + h * 32;
    unsigned aq[4][4];
#pragma unroll
    for (int ks = 0; ks < 4; ++ks) {
        aq[ks][0] = __float_as_uint(q0p[8 * ks + tig]);
        aq[ks][1] = __float_as_uint(q1p[8 * ks + tig]);
        aq[ks][2] = __float_as_uint(q0p[8 * ks + tig + 4]);
        aq[ks][3] = __float_as_uint(q1p[8 * ks + tig + 4]);
    }

    float o[4][4];
#pragma unroll
    for (int nt = 0; nt < 4; ++nt)
#pragma unroll
        for (int q = 0; q < 4; ++q) o[nt][q] = 0.f;
    float m0 = -1e30f, m1 = -1e30f, l0 = 0.f, l1 = 0.f;

    float* Pw = Ps + w * (16 * 34);
    const int ldr = tid >> 3;          // 0..31 (K/V load row)
    const int ldc = (tid & 7) * 4;

    const unsigned ks_base = (unsigned)__cvta_generic_to_shared(Ks) + (ldr * KVST + ldc) * 4;
    const unsigned vs_base = (unsigned)__cvta_generic_to_shared(Vs) + (ldr * KVST + ldc) * 4;
    const size_t   g_off   = (size_t)(b * LM + ldr) * 64 + h * 32 + ldc;

    // prefetch chunk 0 -> buf 0
    {
        int src = ldr;
        int sz = (src < LM) ? 16 : 0;
        cp_async16(ks_base, gk + g_off, sz);
        cp_async16(vs_base, gv + g_off, sz);
    }
    cp_commit();

    for (int c = 0; c < NCH; ++c) {
        const int c0  = c * 32;
        const int buf = c & 1;
        // issue prefetch of chunk c+1 into the other buffer
        if (c + 1 < NCH) {
            int src = c0 + 32 + ldr;
            int sz  = (src < LM) ? 16 : 0;
            unsigned bo = (buf ^ 1) * (32 * KVST * 4);
            size_t go = g_off + (size_t)(c0 + 32) * 64;
            cp_async16(ks_base + bo, gk + go, sz);
            cp_async16(vs_base + bo, gv + go, sz);
        }
        cp_commit();
        cp_wait1();        // chunk c's group complete (c+1 may be in flight)
        __syncthreads();

        const float* Kb = Ks + buf * (32 * KVST);
        const float* Vb = Vs + buf * (32 * KVST);

        // ---- S = Q @ K^T (16 mma) ----
        float s[4][4];
#pragma unroll
        for (int nt = 0; nt < 4; ++nt) {
            s[nt][0] = s[nt][1] = s[nt][2] = s[nt][3] = 0.f;
            const float* kr = Kb + (nt * 8 + gid) * KVST;
#pragma unroll
            for (int ks = 0; ks < 4; ++ks) {
                unsigned b0 = __float_as_uint(kr[8 * ks + tig]);
                unsigned b1 = __float_as_uint(kr[8 * ks + tig + 4]);
                mma_tf32(s[nt], aq[ks], b0, b1);
            }
        }

        // ---- scale + mask + row max ----
        float m0loc = -1e30f, m1loc = -1e30f;
#pragma unroll
        for (int nt = 0; nt < 4; ++nt) {
            int key = c0 + nt * 8 + 2 * tig;
            bool k0v = key < LM, k1v = (key + 1) < LM;
            s[nt][0] = k0v ? s[nt][0] * SCALE : -1e30f;
            s[nt][1] = k1v ? s[nt][1] * SCALE : -1e30f;
            s[nt][2] = k0v ? s[nt][2] * SCALE : -1e30f;
            s[nt][3] = k1v ? s[nt][3] * SCALE : -1e30f;
            m0loc = fmaxf(m0loc, fmaxf(s[nt][0], s[nt][1]));
            m1loc = fmaxf(m1loc, fmaxf(s[nt][2], s[nt][3]));
        }
        m0loc = fmaxf(m0loc, __shfl_xor_sync(0xffffffffu, m0loc, 1));
        m0loc = fmaxf(m0loc, __shfl_xor_sync(0xffffffffu, m0loc, 2));
        m1loc = fmaxf(m1loc, __shfl_xor_sync(0xffffffffu, m1loc, 1));
        m1loc = fmaxf(m1loc, __shfl_xor_sync(0xffffffffu, m1loc, 2));
        float mn0 = fmaxf(m0, m0loc), mn1 = fmaxf(m1, m1loc);
        float cr0 = __expf(m0 - mn0), cr1 = __expf(m1 - mn1);

        // ---- P = exp(s - m) staged to per-warp smem ----
        float ls0 = 0.f, ls1 = 0.f;
#pragma unroll
        for (int nt = 0; nt < 4; ++nt) {
            float p00 = __expf(s[nt][0] - mn0);
            float p01 = __expf(s[nt][1] - mn0);
            float p10 = __expf(s[nt][2] - mn1);
            float p11 = __expf(s[nt][3] - mn1);
            ls0 += p00 + p01;
            ls1 += p10 + p11;
            *(float2*)(Pw + gid * 34 + nt * 8 + 2 * tig)       = make_float2(p00, p01);
            *(float2*)(Pw + (gid + 8) * 34 + nt * 8 + 2 * tig) = make_float2(p10, p11);
        }
        ls0 += __shfl_xor_sync(0xffffffffu, ls0, 1);
        ls0 += __shfl_xor_sync(0xffffffffu, ls0, 2);
        ls1 += __shfl_xor_sync(0xffffffffu, ls1, 1);
        ls1 += __shfl_xor_sync(0xffffffffu, ls1, 2);
        l0 = l0 * cr0 + ls0;
        l1 = l1 * cr1 + ls1;
#pragma unroll
        for (int nt = 0; nt < 4; ++nt) {
            o[nt][0] *= cr0; o[nt][1] *= cr0;
            o[nt][2] *= cr1; o[nt][3] *= cr1;
        }
        m0 = mn0; m1 = mn1;
        __syncwarp();

        // ---- O += P @ V (16 mma) ----
#pragma unroll
        for (int ks = 0; ks < 4; ++ks) {
            unsigned ap[4];
            ap[0] = __float_as_uint(Pw[gid * 34 + 8 * ks + tig]);
            ap[1] = __float_as_uint(Pw[(gid + 8) * 34 + 8 * ks + tig]);
            ap[2] = __float_as_uint(Pw[gid * 34 + 8 * ks + tig + 4]);
            ap[3] = __float_as_uint(Pw[(gid + 8) * 34 + 8 * ks + tig + 4]);
            const float* vr0 = Vb + (8 * ks + tig) * KVST;
            const float* vr1 = Vb + (8 * ks + tig + 4) * KVST;
#pragma unroll
            for (int nt = 0; nt < 4; ++nt) {
                unsigned b0 = __float_as_uint(vr0[nt * 8 + gid]);
                unsigned b1 = __float_as_uint(vr1[nt * 8 + gid]);
                mma_tf32(o[nt], ap, b0, b1);
            }
        }
        __syncthreads();   // all reads of buf c done before cp.async overwrites it
    }

    // ---- normalize + store ----
    float i0 = 1.f / l0, i1 = 1.f / l1;
    if (v0) {
        float* op = g_cat + (size_t)(b * NTOT + r0) * 128 + QOFS + h * 32;
#pragma unroll
        for (int nt = 0; nt < 4; ++nt)
            *(float2*)(op + nt * 8 + 2 * tig) = make_float2(o[nt][0] * i0, o[nt][1] * i0);
    }
    if (v1) {
        float* op = g_cat + (size_t)(b * NTOT + r1) * 128 + QOFS + h * 32;
#pragma unroll
        for (int nt = 0; nt < 4; ++nt)
            *(float2*)(op + nt * 8 + 2 * tig) = make_float2(o[nt][2] * i1, o[nt][3] * i1);
    }
}

__global__ void __launch_bounds__(256, 2) attn_all()
{
    __shared__ __align__(16) float Ks[2 * 32 * KVST];
    __shared__ __align__(16) float Vs[2 * 32 * KVST];
    __shared__ __align__(16) float Ps[8 * 16 * 34];
    if (blockIdx.z == 0) attn_dev<0>(Ks, Vs, Ps);
    else                 attn_dev<1>(Ks, Vs, Ps);
}

// ---------------------------------------------------------------------------
// Launch
// ---------------------------------------------------------------------------
extern "C" void kernel_launch(void* const* d_in, const int* in_sizes, int n_in,
                              void* d_out, int out_size)
{
    (void)in_sizes; (void)n_in; (void)out_size;
    const float* x     = (const float*)d_in[0];
    const float* msg   = (const float*)d_in[1];
    const float* Wq    = (const float*)d_in[2];
    const float* bq    = (const float*)d_in[3];
    const float* sr1w  = (const float*)d_in[4];
    const float* sr1b  = (const float*)d_in[5];
    const float* ln1g  = (const float*)d_in[6];
    const float* ln1b  = (const float*)d_in[7];
    const float* sr2w  = (const float*)d_in[8];
    const float* sr2b  = (const float*)d_in[9];
    const float* ln2g  = (const float*)d_in[10];
    const float* ln2b  = (const float*)d_in[11];
    const float* kv1w  = (const float*)d_in[12];
    const float* kv1b  = (const float*)d_in[13];
    const float* kv2w  = (const float*)d_in[14];
    const float* kv2b  = (const float*)d_in[15];
    const float* lc1w  = (const float*)d_in[16];
    const float* lc1b  = (const float*)d_in[17];
    const float* lc2w  = (const float*)d_in[18];
    const float* lc2b  = (const float*)d_in[19];
    const float* projw = (const float*)d_in[20];
    const float* projb = (const float*)d_in[21];
    float* out = (float*)d_out;

    // SR conv weight repack (both)
    repack_all<<<1280, 256>>>(sr1w, sr2w);

    // Fused: SR1 split-K + SR2 split-K + Q projection (tf32 mma)
    phase1_k<<<523, 256>>>(x, msg, Wq, bq);

    // Fused reduce + bias + LN + GELU
    finish_all<<<1288, 256>>>(sr1b, ln1g, ln1b, sr2b, ln2g, ln2b);

    // Fused KV projections (tf32 mma)
    kv_k<<<82, 256>>>(x, msg, kv1w, kv1b, kv2w, kv2b);

    // Fused depthwise 3x3 V fix-up
    lc_all<<<2576, 256>>>(lc1w, lc1b, lc2w, lc2b);

    // Tensor-core flash attention, cp.async double-buffered (both branches)
    attn_all<<<dim3(33, 16, 2), 256>>>();

    // Output projection + residual + split store (tf32 mma)
    out_k<<<257, 256>>>(x, msg, projw, projb, out);
}

// round 13
// speedup vs baseline: 2.8380x; 1.0412x over previous
#include <cuda_runtime.h>
#include <math.h>

typedef unsigned long long ull;

// ---------------------------------------------------------------------------
// mma / cp.async helpers
// ---------------------------------------------------------------------------
__device__ __forceinline__ void mma_tf32(float* c, const unsigned* a, unsigned b0, unsigned b1) {
    asm volatile(
        "mma.sync.aligned.m16n8k8.row.col.f32.tf32.tf32.f32 "
        "{%0,%1,%2,%3},{%4,%5,%6,%7},{%8,%9},{%0,%1,%2,%3};"
        : "+f"(c[0]), "+f"(c[1]), "+f"(c[2]), "+f"(c[3])
        : "r"(a[0]), "r"(a[1]), "r"(a[2]), "r"(a[3]), "r"(b0), "r"(b1));
}
__device__ __forceinline__ void cp_async16(unsigned saddr, const void* gptr, int sz) {
    asm volatile("cp.async.cg.shared.global [%0], [%1], 16, %2;"
                 :: "r"(saddr), "l"(gptr), "r"(sz));
}
__device__ __forceinline__ void cp_commit() { asm volatile("cp.async.commit_group;"); }
__device__ __forceinline__ void cp_wait1()  { asm volatile("cp.async.wait_group 1;"); }

// ---------------------------------------------------------------------------
// Problem constants
// ---------------------------------------------------------------------------
constexpr int Bb   = 8;
constexpr int Cc   = 128;
constexpr int N0   = 4096;
constexpr int MSGN = 4;
constexpr int NTOT = N0 + MSGN;  // 4100
constexpr int Wimg = 64;
constexpr int MTOT = Bb * NTOT;  // 32800
constexpr size_t OUT2_OFS = (size_t)Bb * N0 * Cc;
constexpr int KVST = 36;             // attention K/V smem row stride
constexpr int GST  = 36;             // GEMM tile smem row stride (16B aligned)
constexpr int GBUF = 128 * GST;      // floats per tile buffer
constexpr int GEMM_SMEM_BYTES = 2 * 2 * GBUF * 4;  // 73728

template <int BR> struct BrCfg;
template <> struct BrCfg<0> {
    static constexpr int S = 4, WR = 16, L = 256, LM = 260, K = 2048, NSPLIT = 8, M = Bb * 260;
};
template <> struct BrCfg<1> {
    static constexpr int S = 2, WR = 32, L = 1024, LM = 1028, K = 512, NSPLIT = 2, M = Bb * 1028;
};

// ---------------------------------------------------------------------------
// Scratch (device globals — no allocation allowed)
// ---------------------------------------------------------------------------
__device__ float g_q  [MTOT * Cc];
__device__ float g_cat[MTOT * Cc];
__device__ float g_w1r[128 * 2048];
__device__ float g_w2r[128 * 512];
__device__ float g_p1 [8 * 2080 * 128];
__device__ float g_p2 [2 * 8224 * 128];
__device__ float g_xk1[2080 * 128];
__device__ float g_xk2[8224 * 128];
__device__ float g_k1 [2080 * 64];
__device__ float g_vt1[2080 * 64];
__device__ float g_v1 [2080 * 64];
__device__ float g_k2 [8224 * 64];
__device__ float g_vt2[8224 * 64];
__device__ float g_v2 [8224 * 64];

// ---------------------------------------------------------------------------
// Weight repack (both SR convs): sr_w[o][c][p] -> wr[o][p*128 + c]
// ---------------------------------------------------------------------------
__global__ void repack_all(const float* __restrict__ s1, const float* __restrict__ s2) {
    int idx = blockIdx.x * 256 + threadIdx.x;
    constexpr int T1 = 128 * 16 * 128;
    constexpr int T2 = 128 * 4  * 128;
    if (idx < T1) {
        int o = idx / (16 * 128);
        int rem = idx % (16 * 128);
        int p = rem / 128, c = rem % 128;
        g_w1r[idx] = s1[(o * 128 + c) * 16 + p];
    } else if (idx < T1 + T2) {
        int j = idx - T1;
        int o = j / (4 * 128);
        int rem = j % (4 * 128);
        int p = rem / 128, c = rem % 128;
        g_w2r[j] = s2[(o * 128 + c) * 4 + p];
    }
}

// ---------------------------------------------------------------------------
// tf32 tensor-core GEMM, cp.async double-buffered natural-layout tiles.
// C[M,128] = A[M,K] @ W[128,K]^T
//  MODE 0: Q proj -> g_q (+bias)        MODE 1: SR split-K partials -> g_p
//  MODE 2: KV proj -> g_k/g_vt (+bias)  MODE 3: out proj -> d_out (+bias+res)
// smem: sA[2][128][GST], sW[2][128][GST]; fragment LDS conflict-free.
// ---------------------------------------------------------------------------
template <int MODE, int BR>
__device__ __forceinline__ void gemm_dev(
    float* sA, float* sW,
    const float* __restrict__ x, const float* __restrict__ msg,
    const float* __restrict__ Wext, const float* __restrict__ bias,
    float* __restrict__ outext,
    int M, int Ktot, int tileM, int kb, int Ks, int splitIdx)
{
    const int tid = threadIdx.x;
    const float* Wp = (MODE == 1) ? (BR ? g_w2r : g_w1r) : Wext;

    // ---- per-thread cp.async assignment: row = tid>>1, half-row of 16 floats ----
    const int lrow = tid >> 1;
    const int lcol = (tid & 1) * 16;

    const float* arow = nullptr;   // row base incl. lcol (k-offset added per iter)
    bool aval = false, aspat_r = true;
    {
        int grow = tileM + lrow;
        aval = grow < M;
        int g2 = aval ? grow : 0;
        if (MODE == 0) {
            int b = g2 / NTOT, n = g2 % NTOT;
            arow = (n < N0)
                ? x   + (size_t)(b * N0   + n)        * 128 + lcol
                : msg + (size_t)(b * MSGN + (n - N0)) * 128 + lcol;
        } else if (MODE == 2) {
            const float* A = BR ? g_xk2 : g_xk1;
            arow = A + (size_t)g2 * 128 + lcol;
        } else if (MODE == 3) {
            arow = g_cat + (size_t)g2 * 128 + lcol;
        } else {
            constexpr int LMc = BrCfg<BR>::LM, Lc = BrCfg<BR>::L;
            constexpr int WRc = BrCfg<BR>::WR, Sc = BrCfg<BR>::S;
            int b = g2 / LMc, l = g2 % LMc;
            if (l < Lc) {
                int hr = l / WRc, wr = l % WRc;
                arow = x + (size_t)(b * N0 + (hr * Sc) * Wimg + wr * Sc) * 128 + lcol;
            } else {
                arow = msg + (size_t)(b * MSGN + (l - Lc)) * 128 + lcol;
                aspat_r = false;
            }
        }
    }
    const float* wrow = Wp + (size_t)lrow * Ktot + lcol;

    const unsigned sA_s = (unsigned)__cvta_generic_to_shared(sA) + (lrow * GST + lcol) * 4;
    const unsigned sW_s = (unsigned)__cvta_generic_to_shared(sW) + (lrow * GST + lcol) * 4;
    const int asz = aval ? 16 : 0;

    // ---- mma coordinates ----
    const int warp   = tid >> 5;
    const int lane31 = tid & 31;
    const int warp_m = warp >> 1;
    const int warp_n = warp & 1;
    const int gid    = lane31 >> 2;
    const int tig    = lane31 & 3;

    float acc[2][8][4];
#pragma unroll
    for (int mt = 0; mt < 2; ++mt)
#pragma unroll
        for (int nt = 0; nt < 8; ++nt)
#pragma unroll
            for (int q = 0; q < 4; ++q) acc[mt][nt][q] = 0.f;

    const int niter = Ks >> 5;

    // ---- prefetch iteration 0 -> buf 0 ----
    {
        int k0 = kb;
        int aofs = k0;
        if (MODE == 1) {
            constexpr int Sc = BrCfg<BR>::S;
            int p = k0 >> 7, c0 = k0 & 127;
            aofs = aspat_r ? ((p / Sc) * Wimg + (p % Sc)) * 128 + c0 : c0;
        }
        const float* ga = arow + aofs;
        const float* gw = wrow + k0;
#pragma unroll
        for (int i = 0; i < 4; ++i) {
            cp_async16(sA_s + i * 16, ga + i * 4, asz);
            cp_async16(sW_s + i * 16, gw + i * 4, 16);
        }
    }
    cp_commit();

    for (int it = 0; it < niter; ++it) {
        const int buf = it & 1;
        if (it + 1 < niter) {
            int k0 = kb + (it + 1) * 32;
            int aofs = k0;
            if (MODE == 1) {
                constexpr int Sc = BrCfg<BR>::S;
                int p = k0 >> 7, c0 = k0 & 127;
                aofs = aspat_r ? ((p / Sc) * Wimg + (p % Sc)) * 128 + c0 : c0;
            }
            const float* ga = arow + aofs;
            const float* gw = wrow + k0;
            unsigned bo = (buf ^ 1) * (GBUF * 4);
#pragma unroll
            for (int i = 0; i < 4; ++i) {
                cp_async16(sA_s + bo + i * 16, ga + i * 4, asz);
                cp_async16(sW_s + bo + i * 16, gw + i * 4, 16);
            }
        }
        cp_commit();
        cp_wait1();
        __syncthreads();

        const float* sAb = sA + buf * GBUF;
        const float* sWb = sW + buf * GBUF;

#pragma unroll
        for (int ks = 0; ks < 4; ++ks) {
            const int kr0 = ks * 8 + tig;
            unsigned afr[2][4];
#pragma unroll
            for (int mt = 0; mt < 2; ++mt) {
                int m = warp_m * 32 + mt * 16 + gid;
                afr[mt][0] = __float_as_uint(sAb[m * GST + kr0]);
                afr[mt][1] = __float_as_uint(sAb[(m + 8) * GST + kr0]);
                afr[mt][2] = __float_as_uint(sAb[m * GST + kr0 + 4]);
                afr[mt][3] = __float_as_uint(sAb[(m + 8) * GST + kr0 + 4]);
            }
#pragma unroll
            for (int nt = 0; nt < 8; ++nt) {
                int n = warp_n * 64 + nt * 8 + gid;
                unsigned b0 = __float_as_uint(sWb[n * GST + kr0]);
                unsigned b1 = __float_as_uint(sWb[n * GST + kr0 + 4]);
                mma_tf32(acc[0][nt], afr[0], b0, b1);
                mma_tf32(acc[1][nt], afr[1], b0, b1);
            }
        }
        __syncthreads();
    }

    // ---- epilogue ----
    float bs[8][2];
    if (MODE != 1) {
#pragma unroll
        for (int nt = 0; nt < 8; ++nt) {
            int cn = warp_n * 64 + nt * 8 + 2 * tig;
            bs[nt][0] = bias[cn];
            bs[nt][1] = bias[cn + 1];
        }
    }

#pragma unroll
    for (int mt = 0; mt < 2; ++mt)
#pragma unroll
    for (int half = 0; half < 2; ++half) {
        int r = tileM + warp_m * 32 + mt * 16 + half * 8 + gid;
        if (r >= M) continue;
        if (MODE == 0) {
            float* o = g_q + (size_t)r * 128;
#pragma unroll
            for (int nt = 0; nt < 8; ++nt) {
                int cn = warp_n * 64 + nt * 8 + 2 * tig;
                *(float2*)(o + cn) = make_float2(acc[mt][nt][half * 2]     + bs[nt][0],
                                                 acc[mt][nt][half * 2 + 1] + bs[nt][1]);
            }
        } else if (MODE == 1) {
            float* o = (BR ? g_p2 : g_p1) + ((size_t)splitIdx * M + r) * 128;
#pragma unroll
            for (int nt = 0; nt < 8; ++nt) {
                int cn = warp_n * 64 + nt * 8 + 2 * tig;
                *(float2*)(o + cn) = make_float2(acc[mt][nt][half * 2],
                                                 acc[mt][nt][half * 2 + 1]);
            }
        } else if (MODE == 2) {
            float* ok = (BR ? g_k2  : g_k1 ) + (size_t)r * 64;
            float* ov = (BR ? g_vt2 : g_vt1) + (size_t)r * 64;
#pragma unroll
            for (int nt = 0; nt < 8; ++nt) {
                int cn = warp_n * 64 + nt * 8 + 2 * tig;
                float2 v = make_float2(acc[mt][nt][half * 2]     + bs[nt][0],
                                       acc[mt][nt][half * 2 + 1] + bs[nt][1]);
                if (cn < 64) *(float2*)(ok + cn)      = v;
                else         *(float2*)(ov + cn - 64) = v;
            }
        } else {
            int b = r / NTOT, n = r % NTOT;
            const float* res;
            float* o;
            if (n < N0) {
                res = x      + (size_t)(b * N0 + n) * 128;
                o   = outext + (size_t)(b * N0 + n) * 128;
            } else {
                res = msg    + (size_t)(b * MSGN + (n - N0)) * 128;
                o   = outext + OUT2_OFS + (size_t)(b * MSGN + (n - N0)) * 128;
            }
#pragma unroll
            for (int nt = 0; nt < 8; ++nt) {
                int cn = warp_n * 64 + nt * 8 + 2 * tig;
                float2 rv = *(const float2*)(res + cn);
                *(float2*)(o + cn) = make_float2(acc[mt][nt][half * 2]     + bs[nt][0] + rv.x,
                                                 acc[mt][nt][half * 2 + 1] + bs[nt][1] + rv.y);
            }
        }
    }
}

// ---------------------------------------------------------------------------
// Phase-1 fused: SR1 split-K (136) + SR2 split-K (130) + Qproj (257)
// ---------------------------------------------------------------------------
__global__ void __launch_bounds__(256, 2) phase1_k(
    const float* __restrict__ x, const float* __restrict__ msg,
    const float* __restrict__ Wq, const float* __restrict__ bq)
{
    extern __shared__ float smem[];
    float* sA = smem;
    float* sW = smem + 2 * GBUF;
    int bx = blockIdx.x;
    if (bx < 136) {
        gemm_dev<1, 0>(sA, sW, x, msg, nullptr, nullptr, nullptr,
                       2080, 2048, (bx % 17) * 128, (bx / 17) * 256, 256, bx / 17);
    } else if (bx < 266) {
        int t = bx - 136;
        gemm_dev<1, 1>(sA, sW, x, msg, nullptr, nullptr, nullptr,
                       8224, 512, (t % 65) * 128, (t / 65) * 256, 256, t / 65);
    } else {
        int t = bx - 266;
        gemm_dev<0, 0>(sA, sW, x, msg, Wq, bq, nullptr,
                       MTOT, 128, t * 128, 0, 128, 0);
    }
}

__global__ void __launch_bounds__(256, 2) kv_k(
    const float* __restrict__ x, const float* __restrict__ msg,
    const float* __restrict__ kv1w, const float* __restrict__ kv1b,
    const float* __restrict__ kv2w, const float* __restrict__ kv2b)
{
    extern __shared__ float smem[];
    float* sA = smem;
    float* sW = smem + 2 * GBUF;
    int bx = blockIdx.x;
    if (bx < 17)
        gemm_dev<2, 0>(sA, sW, x, msg, kv1w, kv1b, nullptr, 2080, 128, bx * 128, 0, 128, 0);
    else
        gemm_dev<2, 1>(sA, sW, x, msg, kv2w, kv2b, nullptr, 8224, 128, (bx - 17) * 128, 0, 128, 0);
}

__global__ void __launch_bounds__(256, 2) out_k(
    const float* __restrict__ x, const float* __restrict__ msg,
    const float* __restrict__ pw, const float* __restrict__ pb,
    float* __restrict__ out)
{
    extern __shared__ float smem[];
    float* sA = smem;
    float* sW = smem + 2 * GBUF;
    gemm_dev<3, 0>(sA, sW, x, msg, pw, pb, out, MTOT, 128, blockIdx.x * 128, 0, 128, 0);
}

// ---------------------------------------------------------------------------
// Split-K reduce + bias + LayerNorm + exact GELU -> g_xk (both branches fused)
// ---------------------------------------------------------------------------
template <int BR>
__device__ __forceinline__ void sr_finish_dev(
    const float* __restrict__ bias, const float* __restrict__ lng,
    const float* __restrict__ lnb, int blk)
{
    constexpr int M  = BrCfg<BR>::M;
    constexpr int NS = BrCfg<BR>::NSPLIT;
    const float* part = BR ? g_p2 : g_p1;
    float* out        = BR ? g_xk2 : g_xk1;

    int warp  = threadIdx.x >> 5;
    int lanei = threadIdx.x & 31;
    int r = blk * 8 + warp;
    if (r >= M) return;

    float v[4];
    {
        float4 a = *(const float4*)(part + (size_t)r * 128 + lanei * 4);
        v[0] = a.x; v[1] = a.y; v[2] = a.z; v[3] = a.w;
    }
#pragma unroll
    for (int s = 1; s < NS; ++s) {
        float4 a = *(const float4*)(part + ((size_t)s * M + r) * 128 + lanei * 4);
        v[0] += a.x; v[1] += a.y; v[2] += a.z; v[3] += a.w;
    }
    {
        float4 bv = *(const float4*)(bias + lanei * 4);
        v[0] += bv.x; v[1] += bv.y; v[2] += bv.z; v[3] += bv.w;
    }
    float sum = v[0] + v[1] + v[2] + v[3];
    float sq  = v[0]*v[0] + v[1]*v[1] + v[2]*v[2] + v[3]*v[3];
#pragma unroll
    for (int ofs = 16; ofs >= 1; ofs >>= 1) {
        sum += __shfl_xor_sync(0xffffffffu, sum, ofs);
        sq  += __shfl_xor_sync(0xffffffffu, sq,  ofs);
    }
    float mean = sum * (1.f / 128.f);
    float var  = sq  * (1.f / 128.f) - mean * mean;
    float rstd = rsqrtf(var + 1e-5f);

    float4 gg = *(const float4*)(lng + lanei * 4);
    float4 bb = *(const float4*)(lnb + lanei * 4);
    float gv[4]  = {gg.x, gg.y, gg.z, gg.w};
    float bv2[4] = {bb.x, bb.y, bb.z, bb.w};
    float ov[4];
#pragma unroll
    for (int q2 = 0; q2 < 4; ++q2) {
        float t = (v[q2] - mean) * rstd * gv[q2] + bv2[q2];
        ov[q2] = 0.5f * t * (1.f + erff(t * 0.70710678118654752f));
    }
    *(float4*)(out + (size_t)r * 128 + lanei * 4) = make_float4(ov[0], ov[1], ov[2], ov[3]);
}

__global__ void finish_all(
    const float* __restrict__ b1, const float* __restrict__ g1, const float* __restrict__ lb1,
    const float* __restrict__ b2, const float* __restrict__ g2, const float* __restrict__ lb2)
{
    if (blockIdx.x < 260) sr_finish_dev<0>(b1, g1, lb1, blockIdx.x);
    else                  sr_finish_dev<1>(b2, g2, lb2, blockIdx.x - 260);
}

// ---------------------------------------------------------------------------
// V fix-up: spatial rows -> v + dwconv3x3(v) + lc_b ; msg rows -> 2*v (fused)
// ---------------------------------------------------------------------------
template <int BR>
__device__ __forceinline__ void lc_dev(const float* __restrict__ lw,
                                       const float* __restrict__ lb, int idx)
{
    constexpr int LM = BrCfg<BR>::LM, L = BrCfg<BR>::L, WR = BrCfg<BR>::WR;
    const float* vt = BR ? g_vt2 : g_vt1;
    float* vo       = BR ? g_v2  : g_v1;
    if (idx >= Bb * LM * 64) return;
    int ch   = idx & 63;
    int rest = idx >> 6;
    int l = rest % LM, b = rest / LM;
    float c = vt[idx];
    if (l >= L) { vo[idx] = 2.f * c; return; }
    int hr = l / WR, wr = l % WR;
    float a = lb[ch];
#pragma unroll
    for (int di = 0; di < 3; ++di)
#pragma unroll
        for (int dj = 0; dj < 3; ++dj) {
            int nh = hr + di - 1, nw = wr + dj - 1;
            if (nh >= 0 && nh < WR && nw >= 0 && nw < WR)
                a += vt[((size_t)(b * LM) + nh * WR + nw) * 64 + ch] * lw[ch * 9 + di * 3 + dj];
        }
    vo[idx] = c + a;
}

__global__ void lc_all(const float* __restrict__ w1, const float* __restrict__ b1,
                       const float* __restrict__ w2, const float* __restrict__ b2)
{
    int bx = blockIdx.x;
    if (bx < 520) lc_dev<0>(w1, b1, bx * 256 + threadIdx.x);
    else          lc_dev<1>(w2, b2, (bx - 520) * 256 + threadIdx.x);
}

// ---------------------------------------------------------------------------
// Tensor-core flash attention, double-buffered cp.async K/V prefetch.
// ---------------------------------------------------------------------------
template <int BR>
__device__ __forceinline__ void attn_dev(float* Ks, float* Vs, float* Ps)
{
    constexpr int LM   = BrCfg<BR>::LM;
    constexpr int NCH  = (LM + 31) / 32;
    constexpr int QOFS = BR ? 64 : 0;
    constexpr float SCALE = 0.17677669529663687f;  // 32^-0.5
    const float* gk = BR ? g_k2 : g_k1;
    const float* gv = BR ? g_v2 : g_v1;

    const int b      = blockIdx.y >> 1;
    const int h      = blockIdx.y & 1;
    const int tid    = threadIdx.x;
    const int w      = tid >> 5;
    const int lane31 = tid & 31;
    const int gid    = lane31 >> 2;
    const int tig    = lane31 & 3;

    const int qbase = blockIdx.x * 128 + w * 16;
    const int r0 = qbase + gid, r1 = qbase + gid + 8;
    const bool v0 = r0 < NTOT, v1 = r1 < NTOT;
    const int rc0 = v0 ? r0 : NTOT - 1, rc1 = v1 ? r1 : NTOT - 1;

    const float* q0p = g_q + (size_t)(b * NTOT + rc0) * 128 + QOFS + h * 32;
    const float* q1p = g_q + (size_t)(b * NTOT + rc1) * 128 + QOFS + h * 32;
    unsigned aq[4][4];
#pragma unroll
    for (int ks = 0; ks < 4; ++ks) {
        aq[ks][0] = __float_as_uint(q0p[8 * ks + tig]);
        aq[ks][1] = __float_as_uint(q1p[8 * ks + tig]);
        aq[ks][2] = __float_as_uint(q0p[8 * ks + tig + 4]);
        aq[ks][3] = __float_as_uint(q1p[8 * ks + tig + 4]);
    }

    float o[4][4];
#pragma unroll
    for (int nt = 0; nt < 4; ++nt)
#pragma unroll
        for (int q = 0; q < 4; ++q) o[nt][q] = 0.f;
    float m0 = -1e30f, m1 = -1e30f, l0 = 0.f, l1 = 0.f;

    float* Pw = Ps + w * (16 * 34);
    const int ldr = tid >> 3;
    const int ldc = (tid & 7) * 4;

    const unsigned ks_base = (unsigned)__cvta_generic_to_shared(Ks) + (ldr * KVST + ldc) * 4;
    const unsigned vs_base = (unsigned)__cvta_generic_to_shared(Vs) + (ldr * KVST + ldc) * 4;
    const size_t   g_off   = (size_t)(b * LM + ldr) * 64 + h * 32 + ldc;

    {
        int sz = (ldr < LM) ? 16 : 0;
        cp_async16(ks_base, gk + g_off, sz);
        cp_async16(vs_base, gv + g_off, sz);
    }
    cp_commit();

    for (int c = 0; c < NCH; ++c) {
        const int c0  = c * 32;
        const int buf = c & 1;
        if (c + 1 < NCH) {
            int src = c0 + 32 + ldr;
            int sz  = (src < LM) ? 16 : 0;
            unsigned bo = (buf ^ 1) * (32 * KVST * 4);
            size_t go = g_off + (size_t)(c0 + 32) * 64;
            cp_async16(ks_base + bo, gk + go, sz);
            cp_async16(vs_base + bo, gv + go, sz);
        }
        cp_commit();
        cp_wait1();
        __syncthreads();

        const float* Kb = Ks + buf * (32 * KVST);
        const float* Vb = Vs + buf * (32 * KVST);

        float s[4][4];
#pragma unroll
        for (int nt = 0; nt < 4; ++nt) {
            s[nt][0] = s[nt][1] = s[nt][2] = s[nt][3] = 0.f;
            const float* kr = Kb + (nt * 8 + gid) * KVST;
#pragma unroll
            for (int ks = 0; ks < 4; ++ks) {
                unsigned b0 = __float_as_uint(kr[8 * ks + tig]);
                unsigned b1 = __float_as_uint(kr[8 * ks + tig + 4]);
                mma_tf32(s[nt], aq[ks], b0, b1);
            }
        }

        float m0loc = -1e30f, m1loc = -1e30f;
#pragma unroll
        for (int nt = 0; nt < 4; ++nt) {
            int key = c0 + nt * 8 + 2 * tig;
            bool k0v = key < LM, k1v = (key + 1) < LM;
            s[nt][0] = k0v ? s[nt][0] * SCALE : -1e30f;
            s[nt][1] = k1v ? s[nt][1] * SCALE : -1e30f;
            s[nt][2] = k0v ? s[nt][2] * SCALE : -1e30f;
            s[nt][3] = k1v ? s[nt][3] * SCALE : -1e30f;
            m0loc = fmaxf(m0loc, fmaxf(s[nt][0], s[nt][1]));
            m1loc = fmaxf(m1loc, fmaxf(s[nt][2], s[nt][3]));
        }
        m0loc = fmaxf(m0loc, __shfl_xor_sync(0xffffffffu, m0loc, 1));
        m0loc = fmaxf(m0loc, __shfl_xor_sync(0xffffffffu, m0loc, 2));
        m1loc = fmaxf(m1loc, __shfl_xor_sync(0xffffffffu, m1loc, 1));
        m1loc = fmaxf(m1loc, __shfl_xor_sync(0xffffffffu, m1loc, 2));
        float mn0 = fmaxf(m0, m0loc), mn1 = fmaxf(m1, m1loc);
        float cr0 = __expf(m0 - mn0), cr1 = __expf(m1 - mn1);

        float ls0 = 0.f, ls1 = 0.f;
#pragma unroll
        for (int nt = 0; nt < 4; ++nt) {
            float p00 = __expf(s[nt][0] - mn0);
            float p01 = __expf(s[nt][1] - mn0);
            float p10 = __expf(s[nt][2] - mn1);
            float p11 = __expf(s[nt][3] - mn1);
            ls0 += p00 + p01;
            ls1 += p10 + p11;
            *(float2*)(Pw + gid * 34 + nt * 8 + 2 * tig)       = make_float2(p00, p01);
            *(float2*)(Pw + (gid + 8) * 34 + nt * 8 + 2 * tig) = make_float2(p10, p11);
        }
        ls0 += __shfl_xor_sync(0xffffffffu, ls0, 1);
        ls0 += __shfl_xor_sync(0xffffffffu, ls0, 2);
        ls1 += __shfl_xor_sync(0xffffffffu, ls1, 1);
        ls1 += __shfl_xor_sync(0xffffffffu, ls1, 2);
        l0 = l0 * cr0 + ls0;
        l1 = l1 * cr1 + ls1;
#pragma unroll
        for (int nt = 0; nt < 4; ++nt) {
            o[nt][0] *= cr0; o[nt][1] *= cr0;
            o[nt][2] *= cr1; o[nt][3] *= cr1;
        }
        m0 = mn0; m1 = mn1;
        __syncwarp();

#pragma unroll
        for (int ks = 0; ks < 4; ++ks) {
            unsigned ap[4];
            ap[0] = __float_as_uint(Pw[gid * 34 + 8 * ks + tig]);
            ap[1] = __float_as_uint(Pw[(gid + 8) * 34 + 8 * ks + tig]);
            ap[2] = __float_as_uint(Pw[gid * 34 + 8 * ks + tig + 4]);
            ap[3] = __float_as_uint(Pw[(gid + 8) * 34 + 8 * ks + tig + 4]);
            const float* vr0 = Vb + (8 * ks + tig) * KVST;
            const float* vr1 = Vb + (8 * ks + tig + 4) * KVST;
#pragma unroll
            for (int nt = 0; nt < 4; ++nt) {
                unsigned b0 = __float_as_uint(vr0[nt * 8 + gid]);
                unsigned b1 = __float_as_uint(vr1[nt * 8 + gid]);
                mma_tf32(o[nt], ap, b0, b1);
            }
        }
        __syncthreads();
    }

    float i0 = 1.f / l0, i1 = 1.f / l1;
    if (v0) {
        float* op = g_cat + (size_t)(b * NTOT + r0) * 128 + QOFS + h * 32;
#pragma unroll
        for (int nt = 0; nt < 4; ++nt)
            *(float2*)(op + nt * 8 + 2 * tig) = make_float2(o[nt][0] * i0, o[nt][1] * i0);
    }
    if (v1) {
        float* op = g_cat + (size_t)(b * NTOT + r1) * 128 + QOFS + h * 32;
#pragma unroll
        for (int nt = 0; nt < 4; ++nt)
            *(float2*)(op + nt * 8 + 2 * tig) = make_float2(o[nt][2] * i1, o[nt][3] * i1);
    }
}

__global__ void __launch_bounds__(256, 2) attn_all()
{
    __shared__ __align__(16) float Ks[2 * 32 * KVST];
    __shared__ __align__(16) float Vs[2 * 32 * KVST];
    __shared__ __align__(16) float Ps[8 * 16 * 34];
    if (blockIdx.z == 0) attn_dev<0>(Ks, Vs, Ps);
    else                 attn_dev<1>(Ks, Vs, Ps);
}

// ---------------------------------------------------------------------------
// Launch
// ---------------------------------------------------------------------------
extern "C" void kernel_launch(void* const* d_in, const int* in_sizes, int n_in,
                              void* d_out, int out_size)
{
    (void)in_sizes; (void)n_in; (void)out_size;
    const float* x     = (const float*)d_in[0];
    const float* msg   = (const float*)d_in[1];
    const float* Wq    = (const float*)d_in[2];
    const float* bq    = (const float*)d_in[3];
    const float* sr1w  = (const float*)d_in[4];
    const float* sr1b  = (const float*)d_in[5];
    const float* ln1g  = (const float*)d_in[6];
    const float* ln1b  = (const float*)d_in[7];
    const float* sr2w  = (const float*)d_in[8];
    const float* sr2b  = (const float*)d_in[9];
    const float* ln2g  = (const float*)d_in[10];
    const float* ln2b  = (const float*)d_in[11];
    const float* kv1w  = (const float*)d_in[12];
    const float* kv1b  = (const float*)d_in[13];
    const float* kv2w  = (const float*)d_in[14];
    const float* kv2b  = (const float*)d_in[15];
    const float* lc1w  = (const float*)d_in[16];
    const float* lc1b  = (const float*)d_in[17];
    const float* lc2w  = (const float*)d_in[18];
    const float* lc2b  = (const float*)d_in[19];
    const float* projw = (const float*)d_in[20];
    const float* projb = (const float*)d_in[21];
    float* out = (float*)d_out;

    // dynamic smem opt-in (>48KB) for the GEMM kernels
    cudaFuncSetAttribute(phase1_k, cudaFuncAttributeMaxDynamicSharedMemorySize, GEMM_SMEM_BYTES);
    cudaFuncSetAttribute(kv_k,     cudaFuncAttributeMaxDynamicSharedMemorySize, GEMM_SMEM_BYTES);
    cudaFuncSetAttribute(out_k,    cudaFuncAttributeMaxDynamicSharedMemorySize, GEMM_SMEM_BYTES);

    // SR conv weight repack (both)
    repack_all<<<1280, 256>>>(sr1w, sr2w);

    // Fused: SR1 split-K + SR2 split-K + Q projection (tf32 mma, cp.async)
    phase1_k<<<523, 256, GEMM_SMEM_BYTES>>>(x, msg, Wq, bq);

    // Fused reduce + bias + LN + GELU
    finish_all<<<1288, 256>>>(sr1b, ln1g, ln1b, sr2b, ln2g, ln2b);

    // Fused KV projections (tf32 mma, cp.async)
    kv_k<<<82, 256, GEMM_SMEM_BYTES>>>(x, msg, kv1w, kv1b, kv2w, kv2b);

    // Fused depthwise 3x3 V fix-up
    lc_all<<<2576, 256>>>(lc1w, lc1b, lc2w, lc2b);

    // Tensor-core flash attention, cp.async double-buffered (both branches)
    attn_all<<<dim3(33, 16, 2), 256>>>();

    // Output projection + residual + split store (tf32 mma, cp.async)
    out_k<<<257, 256, GEMM_SMEM_BYTES>>>(x, msg, projw, projb, out);
}